// round 3
// baseline (speedup 1.0000x reference)
#include <cuda_runtime.h>

#define N 4096
#define C 64

// ---------------- scratch (device globals; no allocation) ----------------
__device__ float g_E[(size_t)4 * N * N];     // exp(logits) for 4 matrices (256MB)
__device__ float g_Qt[2][N * C];             // Q^T, pre-scaled by 1/8   [n][c]
__device__ float g_Kt[2][N * C];             // K^T                      [n][c]
__device__ float g_V[2][C * N];              // V                        [c][n]
__device__ float g_Vs[4][C * N];             // V / rowsum per matrix    [c][m]
__device__ float g_Prow[4][32][N];           // per-colblock rowsum partials
__device__ float g_rs[4][N];                 // reciprocal row sums
__device__ float g_Sp[2][4][C * N];          // message-passing partials (pair, msplit)
__device__ float g_Y[2][C * N];              // post-projection
__device__ float g_bn[2][2][C];              // {mean, rstd} per pair/channel

// ---------------- K1: QKV projections ----------------
__global__ void __launch_bounds__(256) qkv_kernel(
    const float* __restrict__ Xi, const float* __restrict__ Xj,
    const float* __restrict__ Wq, const float* __restrict__ Wk,
    const float* __restrict__ Wv) {
  __shared__ float Xs[C][128];
  int side = blockIdx.y;
  const float* X = side ? Xj : Xi;
  int n0 = blockIdx.x * 128;
  int t = threadIdx.x;
  for (int i = t; i < C * 32; i += 256) {
    int c = i >> 5, q = i & 31;
    *(float4*)&Xs[c][q * 4] = *(const float4*)&X[c * N + n0 + q * 4];
  }
  __syncthreads();
  int o = t & 63, g = t >> 6;  // o: out channel, g: n-phase (0..3)
  float acc[32];

  // --- Wq ---
  {
#pragma unroll
    for (int k = 0; k < 32; k++) acc[k] = 0.f;
    for (int c = 0; c < C; c++) {
      float w = __ldg(&Wq[o * C + c]);
#pragma unroll
      for (int k = 0; k < 32; k++) acc[k] = fmaf(w, Xs[c][g + 4 * k], acc[k]);
    }
#pragma unroll
    for (int k = 0; k < 32; k++)
      g_Qt[side][(n0 + g + 4 * k) * C + o] = acc[k] * 0.125f;  // / sqrt(C)
  }
  // --- Wk ---
  {
#pragma unroll
    for (int k = 0; k < 32; k++) acc[k] = 0.f;
    for (int c = 0; c < C; c++) {
      float w = __ldg(&Wk[o * C + c]);
#pragma unroll
      for (int k = 0; k < 32; k++) acc[k] = fmaf(w, Xs[c][g + 4 * k], acc[k]);
    }
#pragma unroll
    for (int k = 0; k < 32; k++) g_Kt[side][(n0 + g + 4 * k) * C + o] = acc[k];
  }
  // --- Wv ---
  {
#pragma unroll
    for (int k = 0; k < 32; k++) acc[k] = 0.f;
    for (int c = 0; c < C; c++) {
      float w = __ldg(&Wv[o * C + c]);
#pragma unroll
      for (int k = 0; k < 32; k++) acc[k] = fmaf(w, Xs[c][g + 4 * k], acc[k]);
    }
#pragma unroll
    for (int k = 0; k < 32; k++) g_V[side][o * N + n0 + g + 4 * k] = acc[k];
  }
}

// ---------------- K2: logits GEMM + exp + row-sum partials ----------------
// mat 0: (Qi,Ki)  mat 1: (Qi,Kj)  mat 2: (Qj,Kj)  mat 3: (Qj,Ki)
__global__ void __launch_bounds__(256) gemm_exp_kernel() {
  __shared__ float Qsm[32][132];  // k-major
  __shared__ float Ksm[32][132];
  int mat = blockIdx.z;
  int qs = mat >> 1;
  int ks = (mat == 1 || mat == 2) ? 1 : 0;
  const float* Qt = g_Qt[qs];
  const float* Kt = g_Kt[ks];
  int m0 = blockIdx.y * 128, n0 = blockIdx.x * 128;
  int t = threadIdx.x;
  int tx = t & 15, ty = t >> 4;

  float acc[8][8];
#pragma unroll
  for (int i = 0; i < 8; i++)
#pragma unroll
    for (int j = 0; j < 8; j++) acc[i][j] = 0.f;

  for (int kc = 0; kc < 2; kc++) {
    __syncthreads();
    for (int i = t; i < 1024; i += 256) {  // 128 rows x 8 float4
      int r = i >> 3, kq = i & 7;
      float4 v = *(const float4*)&Qt[(m0 + r) * C + kc * 32 + kq * 4];
      Qsm[kq * 4 + 0][r] = v.x; Qsm[kq * 4 + 1][r] = v.y;
      Qsm[kq * 4 + 2][r] = v.z; Qsm[kq * 4 + 3][r] = v.w;
      float4 u = *(const float4*)&Kt[(n0 + r) * C + kc * 32 + kq * 4];
      Ksm[kq * 4 + 0][r] = u.x; Ksm[kq * 4 + 1][r] = u.y;
      Ksm[kq * 4 + 2][r] = u.z; Ksm[kq * 4 + 3][r] = u.w;
    }
    __syncthreads();
#pragma unroll 8
    for (int k = 0; k < 32; k++) {
      float4 a0 = *(float4*)&Qsm[k][ty * 4];
      float4 a1 = *(float4*)&Qsm[k][64 + ty * 4];
      float4 b0 = *(float4*)&Ksm[k][tx * 4];
      float4 b1 = *(float4*)&Ksm[k][64 + tx * 4];
      float a[8] = {a0.x, a0.y, a0.z, a0.w, a1.x, a1.y, a1.z, a1.w};
      float b[8] = {b0.x, b0.y, b0.z, b0.w, b1.x, b1.y, b1.z, b1.w};
#pragma unroll
      for (int i = 0; i < 8; i++)
#pragma unroll
        for (int j = 0; j < 8; j++) acc[i][j] = fmaf(a[i], b[j], acc[i][j]);
    }
  }

  float* E = &g_E[(size_t)mat * N * N];
  float rp[8];
#pragma unroll
  for (int i = 0; i < 8; i++) {
    int row = (i < 4) ? (ty * 4 + i) : (64 + ty * 4 + (i - 4));
    float4 e0, e1;
    e0.x = __expf(acc[i][0]); e0.y = __expf(acc[i][1]);
    e0.z = __expf(acc[i][2]); e0.w = __expf(acc[i][3]);
    e1.x = __expf(acc[i][4]); e1.y = __expf(acc[i][5]);
    e1.z = __expf(acc[i][6]); e1.w = __expf(acc[i][7]);
    *(float4*)&E[(size_t)(m0 + row) * N + n0 + tx * 4] = e0;
    *(float4*)&E[(size_t)(m0 + row) * N + n0 + 64 + tx * 4] = e1;
    rp[i] = ((e0.x + e0.y) + (e0.z + e0.w)) + ((e1.x + e1.y) + (e1.z + e1.w));
  }
  // reduce row partials over the 16 tx lanes (xor 1..8 stays within tx group)
#pragma unroll
  for (int i = 0; i < 8; i++) {
    float v = rp[i];
    v += __shfl_xor_sync(0xffffffffu, v, 1);
    v += __shfl_xor_sync(0xffffffffu, v, 2);
    v += __shfl_xor_sync(0xffffffffu, v, 4);
    v += __shfl_xor_sync(0xffffffffu, v, 8);
    if (tx == 0) {
      int row = (i < 4) ? (ty * 4 + i) : (64 + ty * 4 + (i - 4));
      g_Prow[mat][blockIdx.x][m0 + row] = v;
    }
  }
}

// ---------------- K3a: reduce row-sum partials -> reciprocal ----------------
__global__ void rowsum_kernel() {
  int id = blockIdx.x * 256 + threadIdx.x;  // 4*4096
  int mat = id >> 12, m = id & 4095;
  float s = 0.f;
#pragma unroll
  for (int b = 0; b < 32; b++) s += g_Prow[mat][b][m];
  g_rs[mat][m] = 1.0f / s;
}

// ---------------- K3b: scale V by reciprocal row sums ----------------
__global__ void vscale_kernel() {
  int id = blockIdx.x * 256 + threadIdx.x;  // 4 * 64 * 4096
  int mat = id >> 18;
  int rem = id & 262143;
  int m = rem & 4095;
  g_Vs[mat][rem] = g_V[mat >> 1][rem] * g_rs[mat][m];
}

// ---------------- K4: message passing  S = Vs_a*E_a + Vs_b*E_b ----------------
__global__ void __launch_bounds__(256) mp_kernel() {
  __shared__ float E1s[16][132], E2s[16][132];
  __shared__ float V1s[16][68], V2s[16][68];
  int n0 = blockIdx.x * 128;
  int msplit = blockIdx.y;  // 0..3
  int pair = blockIdx.z;
  int matA = 2 * pair, matB = 2 * pair + 1;
  const float* E1 = &g_E[(size_t)matA * N * N];
  const float* E2 = &g_E[(size_t)matB * N * N];
  const float* VA = g_Vs[matA];
  const float* VB = g_Vs[matB];
  int t = threadIdx.x, tx = t & 15, ty = t >> 4;

  float acc[4][8];
#pragma unroll
  for (int i = 0; i < 4; i++)
#pragma unroll
    for (int j = 0; j < 8; j++) acc[i][j] = 0.f;

  int mbase = msplit * 1024;
  for (int mc = 0; mc < 1024; mc += 16) {
    __syncthreads();
    for (int i = t; i < 1024; i += 256) {  // 16 m x 64 c
      int mm = i & 15, c = i >> 4;
      V1s[mm][c] = VA[c * N + mbase + mc + mm];
      V2s[mm][c] = VB[c * N + mbase + mc + mm];
    }
    for (int i = t; i < 512; i += 256) {  // 16 rows x 32 float4
      int r = i >> 5, q = i & 31;
      *(float4*)&E1s[r][q * 4] = *(const float4*)&E1[(size_t)(mbase + mc + r) * N + n0 + q * 4];
      *(float4*)&E2s[r][q * 4] = *(const float4*)&E2[(size_t)(mbase + mc + r) * N + n0 + q * 4];
    }
    __syncthreads();
#pragma unroll
    for (int mm = 0; mm < 16; mm++) {
      float4 a1 = *(float4*)&V1s[mm][ty * 4];
      float4 a2 = *(float4*)&V2s[mm][ty * 4];
      float4 b10 = *(float4*)&E1s[mm][tx * 4];
      float4 b11 = *(float4*)&E1s[mm][64 + tx * 4];
      float4 b20 = *(float4*)&E2s[mm][tx * 4];
      float4 b21 = *(float4*)&E2s[mm][64 + tx * 4];
      float aa1[4] = {a1.x, a1.y, a1.z, a1.w};
      float aa2[4] = {a2.x, a2.y, a2.z, a2.w};
      float bb1[8] = {b10.x, b10.y, b10.z, b10.w, b11.x, b11.y, b11.z, b11.w};
      float bb2[8] = {b20.x, b20.y, b20.z, b20.w, b21.x, b21.y, b21.z, b21.w};
#pragma unroll
      for (int i = 0; i < 4; i++)
#pragma unroll
        for (int j = 0; j < 8; j++) {
          acc[i][j] = fmaf(aa1[i], bb1[j], acc[i][j]);
          acc[i][j] = fmaf(aa2[i], bb2[j], acc[i][j]);
        }
    }
  }
  float* Sp = g_Sp[pair][msplit];
#pragma unroll
  for (int i = 0; i < 4; i++) {
    int c = ty * 4 + i;
    float4 w0 = {acc[i][0], acc[i][1], acc[i][2], acc[i][3]};
    float4 w1 = {acc[i][4], acc[i][5], acc[i][6], acc[i][7]};
    *(float4*)&Sp[c * N + n0 + tx * 4] = w0;
    *(float4*)&Sp[c * N + n0 + 64 + tx * 4] = w1;
  }
}

// ---------------- K5: Y = Wp * (S + X) ----------------
__global__ void __launch_bounds__(256) ygemm_kernel(
    const float* __restrict__ Xi, const float* __restrict__ Xj,
    const float* __restrict__ Wpi, const float* __restrict__ Wpj) {
  __shared__ float Ts[C][128];
  __shared__ float Wsm[C][C];
  int pair = blockIdx.y;
  const float* X = pair ? Xj : Xi;
  const float* Wp = pair ? Wpj : Wpi;
  int n0 = blockIdx.x * 128;
  int t = threadIdx.x;
  for (int i = t; i < C * C / 4; i += 256)
    *(float4*)&Wsm[0][i * 4] = *(const float4*)&Wp[i * 4];
  for (int i = t; i < C * 32; i += 256) {
    int c = i >> 5, q = i & 31;
    float4 v = *(const float4*)&X[c * N + n0 + q * 4];
#pragma unroll
    for (int s = 0; s < 4; s++) {
      float4 p = *(const float4*)&g_Sp[pair][s][c * N + n0 + q * 4];
      v.x += p.x; v.y += p.y; v.z += p.z; v.w += p.w;
    }
    *(float4*)&Ts[c][q * 4] = v;
  }
  __syncthreads();
  int n = t & 127, h = t >> 7;  // h: 0/1 -> output channels h*32..h*32+31
  float acc[32];
#pragma unroll
  for (int oo = 0; oo < 32; oo++) acc[oo] = 0.f;
  for (int c = 0; c < C; c++) {
    float x = Ts[c][n];
#pragma unroll
    for (int oo = 0; oo < 32; oo++)
      acc[oo] = fmaf(Wsm[h * 32 + oo][c], x, acc[oo]);
  }
#pragma unroll
  for (int oo = 0; oo < 32; oo++)
    g_Y[pair][(h * 32 + oo) * N + n0 + n] = acc[oo];
}

// ---------------- K6: BN stats (one block per pair/channel) ----------------
__global__ void bnstats_kernel() {
  int pair = blockIdx.x >> 6, c = blockIdx.x & 63;
  const float* y = &g_Y[pair][c * N];
  float s = 0.f, sq = 0.f;
  for (int n = threadIdx.x; n < N; n += 128) {
    float v = y[n];
    s += v;
    sq += v * v;
  }
  __shared__ float rs_[128], rq_[128];
  rs_[threadIdx.x] = s; rq_[threadIdx.x] = sq;
  __syncthreads();
  for (int off = 64; off > 0; off >>= 1) {
    if (threadIdx.x < off) {
      rs_[threadIdx.x] += rs_[threadIdx.x + off];
      rq_[threadIdx.x] += rq_[threadIdx.x + off];
    }
    __syncthreads();
  }
  if (threadIdx.x == 0) {
    float mean = rs_[0] * (1.0f / N);
    float var = rq_[0] * (1.0f / N) - mean * mean;
    g_bn[pair][0][c] = mean;
    g_bn[pair][1][c] = rsqrtf(var + 1e-5f);
  }
}

// ---------------- K7: BN + LeakyReLU + sum ----------------
__global__ void epilogue_kernel(const float* __restrict__ gi, const float* __restrict__ bi,
                                const float* __restrict__ gj, const float* __restrict__ bj,
                                float* __restrict__ out) {
  int id = blockIdx.x * 256 + threadIdx.x;  // 64 * 4096
  int c = id >> 12;
  float yi = g_Y[0][id], yj = g_Y[1][id];
  float vi = (yi - g_bn[0][0][c]) * g_bn[0][1][c] * gi[c] + bi[c];
  float vj = (yj - g_bn[1][0][c]) * g_bn[1][1][c] * gj[c] + bj[c];
  vi = (vi >= 0.f) ? vi : 0.01f * vi;
  vj = (vj >= 0.f) ? vj : 0.01f * vj;
  out[id] = vi + vj;
}

// ---------------- launch ----------------
extern "C" void kernel_launch(void* const* d_in, const int* in_sizes, int n_in,
                              void* d_out, int out_size) {
  const float* Xi = (const float*)d_in[0];
  const float* Xj = (const float*)d_in[1];
  const float* Wq = (const float*)d_in[2];
  const float* Wk = (const float*)d_in[3];
  const float* Wv = (const float*)d_in[4];
  const float* Wpi = (const float*)d_in[5];
  const float* Wpj = (const float*)d_in[6];
  const float* gi = (const float*)d_in[7];
  const float* bi = (const float*)d_in[8];
  const float* gj = (const float*)d_in[9];
  const float* bj = (const float*)d_in[10];
  float* out = (float*)d_out;

  qkv_kernel<<<dim3(32, 2), 256>>>(Xi, Xj, Wq, Wk, Wv);
  gemm_exp_kernel<<<dim3(32, 32, 4), 256>>>();
  rowsum_kernel<<<64, 256>>>();
  vscale_kernel<<<4096, 256>>>();
  mp_kernel<<<dim3(32, 4, 2), 256>>>();
  ygemm_kernel<<<dim3(32, 2), 256>>>(Xi, Xj, Wpi, Wpj);
  bnstats_kernel<<<128, 128>>>();
  epilogue_kernel<<<1024, 256>>>(gi, bi, gj, bj, out);
}

// round 5
// speedup vs baseline: 1.4622x; 1.4622x over previous
#include <cuda_runtime.h>
#include <cuda_bf16.h>
#include <cstdint>

#define N 4096
#define C 64

// ---------------- scratch (device globals; no allocation) ----------------
__device__ __align__(1024) __nv_bfloat16 g_Qhl[2][N][192];  // [q]: 0:64 Qh, 64:128 Ql, 128:192 Qh
__device__ __align__(1024) __nv_bfloat16 g_Khl[2][N][192];  // [k]: 0:64 Kh, 64:128 Kh, 128:192 Kl
__device__ __align__(1024) float g_V[2][C * N];
__device__ __align__(1024) __nv_bfloat16 g_VsA[4][128][N];  // rows 0:64 hi(V/s), 64:128 lo
__device__ __align__(1024) __nv_bfloat16 g_Eh[4][(size_t)N * N];  // [key][query]
__device__ __align__(1024) __nv_bfloat16 g_El[4][(size_t)N * N];
__device__ float g_Prow[4][32][N];   // per-kblk colsum partials (per query)
__device__ float g_rs[4][N];
__device__ __align__(1024) float g_Sp[2][4][C * N];
__device__ float g_Y[2][C * N];
__device__ float g_bn[2][2][C];

// ---------------- helpers ----------------
__device__ __forceinline__ uint32_t smem_u32(const void* p) {
  uint32_t a;
  asm("{ .reg .u64 t; cvta.to.shared.u64 t, %1; cvt.u32.u64 %0, t; }" : "=r"(a) : "l"(p));
  return a;
}
__device__ __forceinline__ void cp16(uint32_t dst, const void* src) {
  asm volatile("cp.async.cg.shared.global [%0], [%1], 16;" :: "r"(dst), "l"(src) : "memory");
}
#define CP_COMMIT() asm volatile("cp.async.commit_group;" ::: "memory")
#define CP_WAIT(n_) asm volatile("cp.async.wait_group %0;" :: "n"(n_) : "memory")

__device__ __forceinline__ void mma16816(float* c, uint32_t a0, uint32_t a1, uint32_t a2,
                                         uint32_t a3, uint32_t b0, uint32_t b1) {
  asm volatile(
      "mma.sync.aligned.m16n8k16.row.col.f32.bf16.bf16.f32 "
      "{%0,%1,%2,%3}, {%4,%5,%6,%7}, {%8,%9}, {%0,%1,%2,%3};"
      : "+f"(c[0]), "+f"(c[1]), "+f"(c[2]), "+f"(c[3])
      : "r"(a0), "r"(a1), "r"(a2), "r"(a3), "r"(b0), "r"(b1));
}
__device__ __forceinline__ uint32_t packbf(float x, float y) {
  __nv_bfloat162 p = __halves2bfloat162(__float2bfloat16(x), __float2bfloat16(y));
  return *(uint32_t*)&p;
}

#define SA 40           // smem chunk row stride in bf16 elements (80B, conflict-free)
#define BUFSZ 20480     // one (A+B) chunk pair: 2 * 128*80

// ---------------- K1: QKV projections (fp32 -> bf16 hi/lo) ----------------
__global__ void __launch_bounds__(256) qkv_kernel(
    const float* __restrict__ Xi, const float* __restrict__ Xj,
    const float* __restrict__ Wq, const float* __restrict__ Wk, const float* __restrict__ Wv) {
  __shared__ float Xs[C][128];
  int side = blockIdx.y;
  const float* X = side ? Xj : Xi;
  int n0 = blockIdx.x * 128, t = threadIdx.x;
  for (int i = t; i < C * 32; i += 256) {
    int c = i >> 5, q = i & 31;
    *(float4*)&Xs[c][q * 4] = *(const float4*)&X[c * N + n0 + q * 4];
  }
  __syncthreads();
  int o = t & 63, g = t >> 6;
  float acc[32];
  {  // Q (scaled 1/8)
#pragma unroll
    for (int k = 0; k < 32; k++) acc[k] = 0.f;
    for (int c = 0; c < C; c++) {
      float w = __ldg(&Wq[o * C + c]);
#pragma unroll
      for (int k = 0; k < 32; k++) acc[k] = fmaf(w, Xs[c][g + 4 * k], acc[k]);
    }
#pragma unroll
    for (int k = 0; k < 32; k++) {
      float v = acc[k] * 0.125f;
      __nv_bfloat16 h = __float2bfloat16(v);
      __nv_bfloat16 L = __float2bfloat16(v - __bfloat162float(h));
      int n = n0 + g + 4 * k;
      g_Qhl[side][n][o] = h; g_Qhl[side][n][64 + o] = L; g_Qhl[side][n][128 + o] = h;
    }
  }
  {  // K
#pragma unroll
    for (int k = 0; k < 32; k++) acc[k] = 0.f;
    for (int c = 0; c < C; c++) {
      float w = __ldg(&Wk[o * C + c]);
#pragma unroll
      for (int k = 0; k < 32; k++) acc[k] = fmaf(w, Xs[c][g + 4 * k], acc[k]);
    }
#pragma unroll
    for (int k = 0; k < 32; k++) {
      float v = acc[k];
      __nv_bfloat16 h = __float2bfloat16(v);
      __nv_bfloat16 L = __float2bfloat16(v - __bfloat162float(h));
      int n = n0 + g + 4 * k;
      g_Khl[side][n][o] = h; g_Khl[side][n][64 + o] = h; g_Khl[side][n][128 + o] = L;
    }
  }
  {  // V fp32
#pragma unroll
    for (int k = 0; k < 32; k++) acc[k] = 0.f;
    for (int c = 0; c < C; c++) {
      float w = __ldg(&Wv[o * C + c]);
#pragma unroll
      for (int k = 0; k < 32; k++) acc[k] = fmaf(w, Xs[c][g + 4 * k], acc[k]);
    }
#pragma unroll
    for (int k = 0; k < 32; k++) g_V[side][o * N + n0 + g + 4 * k] = acc[k];
  }
}

// ---------------- K2: logits via mma.sync (D[k][q], K=192) + exp + colsum + E ----------------
// mat 0:(Qi,Ki) 1:(Qi,Kj) 2:(Qj,Kj) 3:(Qj,Ki)
__global__ void __launch_bounds__(256) gemm_exp_mma() {
  __shared__ __align__(16) char SM[2 * BUFSZ];
  int t = threadIdx.x, lane = t & 31, wid = t >> 5;
  int wk = wid & 1, wq = wid >> 1;     // warp tile: 64(k) x 32(q)
  int r = lane >> 2, tq = lane & 3;
  int mat = blockIdx.z, kblk = blockIdx.x, qblk = blockIdx.y;
  int k0 = kblk * 128, q0 = qblk * 128;
  int qs = mat >> 1, ks = (mat == 1 || mat == 2) ? 1 : 0;
  const char* Ag = (const char*)&g_Khl[ks][k0][0];
  const char* Bg = (const char*)&g_Qhl[qs][q0][0];

  float acc[4][4][4];
#pragma unroll
  for (int i = 0; i < 4; i++)
#pragma unroll
    for (int j = 0; j < 4; j++)
#pragma unroll
      for (int v = 0; v < 4; v++) acc[i][j][v] = 0.f;

  // chunk loader: 128 rows x 32 bf16 each for A and B
  {
    char* a = SM; char* b = SM + 10240;
#pragma unroll
    for (int i = 0; i < 2; i++) {
      int idx = t + 256 * i, row = idx >> 2, c16 = idx & 3;
      cp16(smem_u32(a + row * 80 + c16 * 16), Ag + (size_t)row * 384 + c16 * 16);
      cp16(smem_u32(b + row * 80 + c16 * 16), Bg + (size_t)row * 384 + c16 * 16);
    }
    CP_COMMIT();
  }
  for (int ch = 0; ch < 6; ch++) {
    if (ch < 5) {
      char* a = SM + ((ch + 1) & 1) * BUFSZ; char* b = a + 10240;
#pragma unroll
      for (int i = 0; i < 2; i++) {
        int idx = t + 256 * i, row = idx >> 2, c16 = idx & 3;
        cp16(smem_u32(a + row * 80 + c16 * 16), Ag + (size_t)row * 384 + (ch + 1) * 64 + c16 * 16);
        cp16(smem_u32(b + row * 80 + c16 * 16), Bg + (size_t)row * 384 + (ch + 1) * 64 + c16 * 16);
      }
      CP_COMMIT();
      CP_WAIT(1);
    } else {
      CP_WAIT(0);
    }
    __syncthreads();
    const uint32_t* As = (const uint32_t*)(SM + (ch & 1) * BUFSZ);
    const uint32_t* Bs = (const uint32_t*)(SM + (ch & 1) * BUFSZ + 10240);
#pragma unroll
    for (int s16 = 0; s16 < 2; s16++) {
      int f = s16 * 16;
      uint32_t a[4][4], b[4][2];
#pragma unroll
      for (int kf = 0; kf < 4; kf++) {
        int row = wk * 64 + kf * 16 + r;
        a[kf][0] = As[(row * SA + f + 2 * tq) >> 1];
        a[kf][1] = As[((row + 8) * SA + f + 2 * tq) >> 1];
        a[kf][2] = As[(row * SA + f + 2 * tq + 8) >> 1];
        a[kf][3] = As[((row + 8) * SA + f + 2 * tq + 8) >> 1];
      }
#pragma unroll
      for (int qf = 0; qf < 4; qf++) {
        int qr = wq * 32 + qf * 8 + r;
        b[qf][0] = Bs[(qr * SA + f + 2 * tq) >> 1];
        b[qf][1] = Bs[(qr * SA + f + 2 * tq + 8) >> 1];
      }
#pragma unroll
      for (int kf = 0; kf < 4; kf++)
#pragma unroll
        for (int qf = 0; qf < 4; qf++)
          mma16816(acc[kf][qf], a[kf][0], a[kf][1], a[kf][2], a[kf][3], b[qf][0], b[qf][1]);
    }
    __syncthreads();
  }

  // exp + column (query) sums
#pragma unroll
  for (int kf = 0; kf < 4; kf++)
#pragma unroll
    for (int qf = 0; qf < 4; qf++)
#pragma unroll
      for (int v = 0; v < 4; v++) acc[kf][qf][v] = __expf(acc[kf][qf][v]);

  float colp[4][2];
#pragma unroll
  for (int qf = 0; qf < 4; qf++) {
    colp[qf][0] = colp[qf][1] = 0.f;
#pragma unroll
    for (int kf = 0; kf < 4; kf++) {
      colp[qf][0] += acc[kf][qf][0] + acc[kf][qf][2];
      colp[qf][1] += acc[kf][qf][1] + acc[kf][qf][3];
    }
    colp[qf][0] += __shfl_xor_sync(0xffffffffu, colp[qf][0], 4);
    colp[qf][0] += __shfl_xor_sync(0xffffffffu, colp[qf][0], 8);
    colp[qf][0] += __shfl_xor_sync(0xffffffffu, colp[qf][0], 16);
    colp[qf][1] += __shfl_xor_sync(0xffffffffu, colp[qf][1], 4);
    colp[qf][1] += __shfl_xor_sync(0xffffffffu, colp[qf][1], 8);
    colp[qf][1] += __shfl_xor_sync(0xffffffffu, colp[qf][1], 16);
  }
  float* colsum = (float*)(SM + 35840);  // [2][128]
  if (lane < 4) {
#pragma unroll
    for (int qf = 0; qf < 4; qf++) {
      colsum[wk * 128 + wq * 32 + qf * 8 + 2 * tq + 0] = colp[qf][0];
      colsum[wk * 128 + wq * 32 + qf * 8 + 2 * tq + 1] = colp[qf][1];
    }
  }
  // stage HI plane (bf16, [k][q], row stride 136)
  __nv_bfloat16* stg = (__nv_bfloat16*)SM;
#pragma unroll
  for (int kf = 0; kf < 4; kf++)
#pragma unroll
    for (int qf = 0; qf < 4; qf++) {
      int row = wk * 64 + kf * 16 + r, col = wq * 32 + qf * 8 + 2 * tq;
      *(uint32_t*)&stg[row * 136 + col] = packbf(acc[kf][qf][0], acc[kf][qf][1]);
      *(uint32_t*)&stg[(row + 8) * 136 + col] = packbf(acc[kf][qf][2], acc[kf][qf][3]);
    }
  __syncthreads();
  if (t < 128) g_Prow[mat][kblk][q0 + t] = colsum[t] + colsum[128 + t];
#pragma unroll
  for (int i = 0; i < 8; i++) {
    int idx = t + 256 * i, row = idx >> 4, c16 = idx & 15;
    uint4 v = *(const uint4*)(SM + row * 272 + c16 * 16);
    *(uint4*)((char*)&g_Eh[mat][0] + ((size_t)(k0 + row) * N + q0) * 2 + c16 * 16) = v;
  }
  __syncthreads();
  // stage LO plane
#pragma unroll
  for (int kf = 0; kf < 4; kf++)
#pragma unroll
    for (int qf = 0; qf < 4; qf++) {
      int row = wk * 64 + kf * 16 + r, col = wq * 32 + qf * 8 + 2 * tq;
      float e0 = acc[kf][qf][0], e1 = acc[kf][qf][1];
      float e2 = acc[kf][qf][2], e3 = acc[kf][qf][3];
      float l0 = e0 - __bfloat162float(__float2bfloat16(e0));
      float l1 = e1 - __bfloat162float(__float2bfloat16(e1));
      float l2 = e2 - __bfloat162float(__float2bfloat16(e2));
      float l3 = e3 - __bfloat162float(__float2bfloat16(e3));
      *(uint32_t*)&stg[row * 136 + col] = packbf(l0, l1);
      *(uint32_t*)&stg[(row + 8) * 136 + col] = packbf(l2, l3);
    }
  __syncthreads();
#pragma unroll
  for (int i = 0; i < 8; i++) {
    int idx = t + 256 * i, row = idx >> 4, c16 = idx & 15;
    uint4 v = *(const uint4*)(SM + row * 272 + c16 * 16);
    *(uint4*)((char*)&g_El[mat][0] + ((size_t)(k0 + row) * N + q0) * 2 + c16 * 16) = v;
  }
}

// ---------------- K3a: reduce colsum partials ----------------
__global__ void rowsum_kernel() {
  int id = blockIdx.x * 256 + threadIdx.x;
  int mat = id >> 12, m = id & 4095;
  float s = 0.f;
#pragma unroll
  for (int b = 0; b < 32; b++) s += g_Prow[mat][b][m];
  g_rs[mat][m] = 1.0f / s;
}
// ---------------- K3b: Vs = V/rowsum, hi/lo split ----------------
__global__ void vsplit_kernel() {
  int id = blockIdx.x * 256 + threadIdx.x;  // 4*64*2048
  int mat = id >> 17, rem = id & 131071;
  int c = rem >> 11, m = (rem & 2047) * 2;
  float v0 = g_V[mat >> 1][c * N + m] * g_rs[mat][m];
  float v1 = g_V[mat >> 1][c * N + m + 1] * g_rs[mat][m + 1];
  __nv_bfloat16 h0 = __float2bfloat16(v0), h1 = __float2bfloat16(v1);
  __nv_bfloat16 l0 = __float2bfloat16(v0 - __bfloat162float(h0));
  __nv_bfloat16 l1 = __float2bfloat16(v1 - __bfloat162float(h1));
  *(__nv_bfloat162*)&g_VsA[mat][c][m] = __halves2bfloat162(h0, h1);
  *(__nv_bfloat162*)&g_VsA[mat][64 + c][m] = __halves2bfloat162(l0, l1);
}

// ---------------- K4: message passing via mma.sync ----------------
// Out[ch(128 stacked)][n] = sum_m VsA[mat][ch][m] * E_T[mat/plane][n][m]; fold ch/ch+64.
__global__ void __launch_bounds__(256) mp_mma() {
  __shared__ __align__(16) char SM[2 * BUFSZ];
  int t = threadIdx.x, lane = t & 31, wid = t >> 5;
  int wc = wid & 1, wn = wid >> 1;  // warp tile: 64(ch) x 32(n)
  int r = lane >> 2, tq = lane & 3;
  int nblk = blockIdx.x, ms = blockIdx.y, pair = blockIdx.z;
  int n0 = nblk * 128, mbase = ms * 1024;

  float acc[4][4][4];
#pragma unroll
  for (int i = 0; i < 4; i++)
#pragma unroll
    for (int j = 0; j < 4; j++)
#pragma unroll
      for (int v = 0; v < 4; v++) acc[i][j][v] = 0.f;

  // chunk ci: mat = 2*pair + (ci>>6); plane = (ci>>5)&1; mc = ci&31
  {
    const char* Ag = (const char*)&g_VsA[2 * pair][0][0];
    const char* Bg = (const char*)&g_Eh[2 * pair][0];
    int mo = mbase * 2;
    char* a = SM; char* b = SM + 10240;
#pragma unroll
    for (int i = 0; i < 2; i++) {
      int idx = t + 256 * i, row = idx >> 2, c16 = idx & 3;
      cp16(smem_u32(a + row * 80 + c16 * 16), Ag + (size_t)row * 8192 + mo + c16 * 16);
      cp16(smem_u32(b + row * 80 + c16 * 16), Bg + (size_t)(n0 + row) * 8192 + mo + c16 * 16);
    }
    CP_COMMIT();
  }
  for (int ci = 0; ci < 128; ci++) {
    if (ci < 127) {
      int cn = ci + 1;
      int mat = 2 * pair + (cn >> 6), plane = (cn >> 5) & 1, mc = cn & 31;
      const char* Ag = (const char*)&g_VsA[mat][0][0];
      const char* Bg = (const char*)(plane ? &g_El[mat][0] : &g_Eh[mat][0]);
      int mo = (mbase + mc * 32) * 2;
      char* a = SM + (cn & 1) * BUFSZ; char* b = a + 10240;
#pragma unroll
      for (int i = 0; i < 2; i++) {
        int idx = t + 256 * i, row = idx >> 2, c16 = idx & 3;
        cp16(smem_u32(a + row * 80 + c16 * 16), Ag + (size_t)row * 8192 + mo + c16 * 16);
        cp16(smem_u32(b + row * 80 + c16 * 16), Bg + (size_t)(n0 + row) * 8192 + mo + c16 * 16);
      }
      CP_COMMIT();
      CP_WAIT(1);
    } else {
      CP_WAIT(0);
    }
    __syncthreads();
    const uint32_t* As = (const uint32_t*)(SM + (ci & 1) * BUFSZ);
    const uint32_t* Bs = (const uint32_t*)(SM + (ci & 1) * BUFSZ + 10240);
#pragma unroll
    for (int s16 = 0; s16 < 2; s16++) {
      int f = s16 * 16;
      uint32_t a[4][4], b[4][2];
#pragma unroll
      for (int kf = 0; kf < 4; kf++) {
        int row = wc * 64 + kf * 16 + r;
        a[kf][0] = As[(row * SA + f + 2 * tq) >> 1];
        a[kf][1] = As[((row + 8) * SA + f + 2 * tq) >> 1];
        a[kf][2] = As[(row * SA + f + 2 * tq + 8) >> 1];
        a[kf][3] = As[((row + 8) * SA + f + 2 * tq + 8) >> 1];
      }
#pragma unroll
      for (int qf = 0; qf < 4; qf++) {
        int nr = wn * 32 + qf * 8 + r;
        b[qf][0] = Bs[(nr * SA + f + 2 * tq) >> 1];
        b[qf][1] = Bs[(nr * SA + f + 2 * tq + 8) >> 1];
      }
#pragma unroll
      for (int kf = 0; kf < 4; kf++)
#pragma unroll
        for (int qf = 0; qf < 4; qf++)
          mma16816(acc[kf][qf], a[kf][0], a[kf][1], a[kf][2], a[kf][3], b[qf][0], b[qf][1]);
    }
    __syncthreads();
  }

  // fold hi-rows + lo-rows, write fp32 partials
  float* stg = (float*)SM;  // [64][132]
  if (wc == 0) {
#pragma unroll
    for (int kf = 0; kf < 4; kf++)
#pragma unroll
      for (int qf = 0; qf < 4; qf++) {
        int row = kf * 16 + r, col = wn * 32 + qf * 8 + 2 * tq;
        *(float2*)&stg[row * 132 + col] = make_float2(acc[kf][qf][0], acc[kf][qf][1]);
        *(float2*)&stg[(row + 8) * 132 + col] = make_float2(acc[kf][qf][2], acc[kf][qf][3]);
      }
  }
  __syncthreads();
  if (wc == 1) {
#pragma unroll
    for (int kf = 0; kf < 4; kf++)
#pragma unroll
      for (int qf = 0; qf < 4; qf++) {
        int row = kf * 16 + r, col = wn * 32 + qf * 8 + 2 * tq;
        float2 v0 = *(float2*)&stg[row * 132 + col];
        v0.x += acc[kf][qf][0]; v0.y += acc[kf][qf][1];
        *(float2*)&stg[row * 132 + col] = v0;
        float2 v1 = *(float2*)&stg[(row + 8) * 132 + col];
        v1.x += acc[kf][qf][2]; v1.y += acc[kf][qf][3];
        *(float2*)&stg[(row + 8) * 132 + col] = v1;
      }
  }
  __syncthreads();
  float* Sp = g_Sp[pair][ms];
#pragma unroll
  for (int i = 0; i < 8; i++) {
    int idx = t + 256 * i, row = idx >> 5, q4 = idx & 31;
    float4 v = *(float4*)&stg[row * 132 + q4 * 4];
    *(float4*)&Sp[row * N + n0 + q4 * 4] = v;
  }
}

// ---------------- K5: Y = Wp * (S + X) ----------------
__global__ void __launch_bounds__(256) ygemm_kernel(
    const float* __restrict__ Xi, const float* __restrict__ Xj,
    const float* __restrict__ Wpi, const float* __restrict__ Wpj) {
  __shared__ float Ts[C][128];
  __shared__ float Wsm[C][C];
  int pair = blockIdx.y;
  const float* X = pair ? Xj : Xi;
  const float* Wp = pair ? Wpj : Wpi;
  int n0 = blockIdx.x * 128, t = threadIdx.x;
  for (int i = t; i < C * C / 4; i += 256)
    *(float4*)&Wsm[0][i * 4] = *(const float4*)&Wp[i * 4];
  for (int i = t; i < C * 32; i += 256) {
    int c = i >> 5, q = i & 31;
    float4 v = *(const float4*)&X[c * N + n0 + q * 4];
#pragma unroll
    for (int s = 0; s < 4; s++) {
      float4 p = *(const float4*)&g_Sp[pair][s][c * N + n0 + q * 4];
      v.x += p.x; v.y += p.y; v.z += p.z; v.w += p.w;
    }
    *(float4*)&Ts[c][q * 4] = v;
  }
  __syncthreads();
  int n = t & 127, h = t >> 7;
  float acc[32];
#pragma unroll
  for (int oo = 0; oo < 32; oo++) acc[oo] = 0.f;
  for (int c = 0; c < C; c++) {
    float x = Ts[c][n];
#pragma unroll
    for (int oo = 0; oo < 32; oo++) acc[oo] = fmaf(Wsm[h * 32 + oo][c], x, acc[oo]);
  }
#pragma unroll
  for (int oo = 0; oo < 32; oo++) g_Y[pair][(h * 32 + oo) * N + n0 + n] = acc[oo];
}

// ---------------- K6: BN stats ----------------
__global__ void bnstats_kernel() {
  int pair = blockIdx.x >> 6, c = blockIdx.x & 63;
  const float* y = &g_Y[pair][c * N];
  float s = 0.f, sq = 0.f;
  for (int n = threadIdx.x; n < N; n += 128) {
    float v = y[n];
    s += v; sq += v * v;
  }
  __shared__ float rs_[128], rq_[128];
  rs_[threadIdx.x] = s; rq_[threadIdx.x] = sq;
  __syncthreads();
  for (int off = 64; off > 0; off >>= 1) {
    if (threadIdx.x < off) {
      rs_[threadIdx.x] += rs_[threadIdx.x + off];
      rq_[threadIdx.x] += rq_[threadIdx.x + off];
    }
    __syncthreads();
  }
  if (threadIdx.x == 0) {
    float mean = rs_[0] * (1.0f / N);
    float var = rq_[0] * (1.0f / N) - mean * mean;
    g_bn[pair][0][c] = mean;
    g_bn[pair][1][c] = rsqrtf(var + 1e-5f);
  }
}

// ---------------- K7: BN + LeakyReLU + sum ----------------
__global__ void epilogue_kernel(const float* __restrict__ gi, const float* __restrict__ bi,
                                const float* __restrict__ gj, const float* __restrict__ bj,
                                float* __restrict__ out) {
  int id = blockIdx.x * 256 + threadIdx.x;
  int c = id >> 12;
  float yi = g_Y[0][id], yj = g_Y[1][id];
  float vi = (yi - g_bn[0][0][c]) * g_bn[0][1][c] * gi[c] + bi[c];
  float vj = (yj - g_bn[1][0][c]) * g_bn[1][1][c] * gj[c] + bj[c];
  vi = (vi >= 0.f) ? vi : 0.01f * vi;
  vj = (vj >= 0.f) ? vj : 0.01f * vj;
  out[id] = vi + vj;
}

// ---------------- launch ----------------
extern "C" void kernel_launch(void* const* d_in, const int* in_sizes, int n_in,
                              void* d_out, int out_size) {
  const float* Xi = (const float*)d_in[0];
  const float* Xj = (const float*)d_in[1];
  const float* Wq = (const float*)d_in[2];
  const float* Wk = (const float*)d_in[3];
  const float* Wv = (const float*)d_in[4];
  const float* Wpi = (const float*)d_in[5];
  const float* Wpj = (const float*)d_in[6];
  const float* gi = (const float*)d_in[7];
  const float* bi = (const float*)d_in[8];
  const float* gj = (const float*)d_in[9];
  const float* bj = (const float*)d_in[10];
  float* out = (float*)d_out;

  qkv_kernel<<<dim3(32, 2), 256>>>(Xi, Xj, Wq, Wk, Wv);
  gemm_exp_mma<<<dim3(32, 32, 4), 256>>>();
  rowsum_kernel<<<64, 256>>>();
  vsplit_kernel<<<2048, 256>>>();
  mp_mma<<<dim3(32, 4, 2), 256>>>();
  ygemm_kernel<<<dim3(32, 2), 256>>>(Xi, Xj, Wpi, Wpj);
  bnstats_kernel<<<128, 128>>>();
  epilogue_kernel<<<1024, 256>>>(gi, bi, gj, bj, out);
}

// round 6
// speedup vs baseline: 1.8120x; 1.2392x over previous
#include <cuda_runtime.h>
#include <cuda_bf16.h>
#include <cstdint>

#define N 4096
#define C 64

// ---------------- scratch (device globals; no allocation) ----------------
__device__ __align__(1024) __nv_bfloat16 g_Qhl[2][N][192];  // [q]: 0:64 Qh, 64:128 Ql, 128:192 Qh (scaled 1/8)
__device__ __align__(1024) __nv_bfloat16 g_Khl[2][N][192];  // [k]: 0:64 Kh, 64:128 Kh, 128:192 Kl
__device__ __align__(1024) float g_V[2][C * N];
__device__ __align__(1024) __nv_bfloat16 g_Vsb[4][C * N];   // V * (1/rowsum), bf16 hi only
__device__ float g_Prow[4][32][N];   // per-kblk partial sums (per query m)
__device__ float g_rs[4][N];
__device__ __align__(1024) float g_P[4][C * N];  // normalized message-passing output per mat
__device__ float g_Y[2][C * N];
__device__ float g_bn[2][2][C];

// ---------------- helpers ----------------
__device__ __forceinline__ uint32_t smem_u32(const void* p) {
  uint32_t a;
  asm("{ .reg .u64 t; cvta.to.shared.u64 t, %1; cvt.u32.u64 %0, t; }" : "=r"(a) : "l"(p));
  return a;
}
__device__ __forceinline__ void cp16(uint32_t dst, const void* src) {
  asm volatile("cp.async.cg.shared.global [%0], [%1], 16;" :: "r"(dst), "l"(src) : "memory");
}
#define CP_COMMIT() asm volatile("cp.async.commit_group;" ::: "memory")
#define CP_WAIT(n_) asm volatile("cp.async.wait_group %0;" :: "n"(n_) : "memory")

__device__ __forceinline__ void mma16816(float* c, uint32_t a0, uint32_t a1, uint32_t a2,
                                         uint32_t a3, uint32_t b0, uint32_t b1) {
  asm volatile(
      "mma.sync.aligned.m16n8k16.row.col.f32.bf16.bf16.f32 "
      "{%0,%1,%2,%3}, {%4,%5,%6,%7}, {%8,%9}, {%0,%1,%2,%3};"
      : "+f"(c[0]), "+f"(c[1]), "+f"(c[2]), "+f"(c[3])
      : "r"(a0), "r"(a1), "r"(a2), "r"(a3), "r"(b0), "r"(b1));
}
__device__ __forceinline__ uint32_t packbf(float x, float y) {
  __nv_bfloat162 p = __halves2bfloat162(__float2bfloat16(x), __float2bfloat16(y));
  return *(uint32_t*)&p;
}

#define SA 40           // pass-1 smem chunk row stride in bf16 (80B)
#define BUFSZ 20480

// ---------------- K1: QKV projections (fp32 -> bf16 hi/lo) ----------------
__global__ void __launch_bounds__(256) qkv_kernel(
    const float* __restrict__ Xi, const float* __restrict__ Xj,
    const float* __restrict__ Wq, const float* __restrict__ Wk, const float* __restrict__ Wv) {
  __shared__ float Xs[C][128];
  int side = blockIdx.y;
  const float* X = side ? Xj : Xi;
  int n0 = blockIdx.x * 128, t = threadIdx.x;
  for (int i = t; i < C * 32; i += 256) {
    int c = i >> 5, q = i & 31;
    *(float4*)&Xs[c][q * 4] = *(const float4*)&X[c * N + n0 + q * 4];
  }
  __syncthreads();
  int o = t & 63, g = t >> 6;
  float acc[32];
  {  // Q (scaled 1/8)
#pragma unroll
    for (int k = 0; k < 32; k++) acc[k] = 0.f;
    for (int c = 0; c < C; c++) {
      float w = __ldg(&Wq[o * C + c]);
#pragma unroll
      for (int k = 0; k < 32; k++) acc[k] = fmaf(w, Xs[c][g + 4 * k], acc[k]);
    }
#pragma unroll
    for (int k = 0; k < 32; k++) {
      float v = acc[k] * 0.125f;
      __nv_bfloat16 h = __float2bfloat16(v);
      __nv_bfloat16 L = __float2bfloat16(v - __bfloat162float(h));
      int n = n0 + g + 4 * k;
      g_Qhl[side][n][o] = h; g_Qhl[side][n][64 + o] = L; g_Qhl[side][n][128 + o] = h;
    }
  }
  {  // K
#pragma unroll
    for (int k = 0; k < 32; k++) acc[k] = 0.f;
    for (int c = 0; c < C; c++) {
      float w = __ldg(&Wk[o * C + c]);
#pragma unroll
      for (int k = 0; k < 32; k++) acc[k] = fmaf(w, Xs[c][g + 4 * k], acc[k]);
    }
#pragma unroll
    for (int k = 0; k < 32; k++) {
      float v = acc[k];
      __nv_bfloat16 h = __float2bfloat16(v);
      __nv_bfloat16 L = __float2bfloat16(v - __bfloat162float(h));
      int n = n0 + g + 4 * k;
      g_Khl[side][n][o] = h; g_Khl[side][n][64 + o] = h; g_Khl[side][n][128 + o] = L;
    }
  }
  {  // V fp32
#pragma unroll
    for (int k = 0; k < 32; k++) acc[k] = 0.f;
    for (int c = 0; c < C; c++) {
      float w = __ldg(&Wv[o * C + c]);
#pragma unroll
      for (int k = 0; k < 32; k++) acc[k] = fmaf(w, Xs[c][g + 4 * k], acc[k]);
    }
#pragma unroll
    for (int k = 0; k < 32; k++) g_V[side][o * N + n0 + g + 4 * k] = acc[k];
  }
}

// ---------------- K2 (pass 1): logits K=192 + exp + rowsum partials only ----------------
// mat 0:(Qi,Ki) 1:(Qi,Kj) 2:(Qj,Kj) 3:(Qj,Ki); D[k][q]; s[q] = sum over k
__global__ void __launch_bounds__(256) pass1_logits() {
  __shared__ __align__(16) char SM[2 * BUFSZ];
  int t = threadIdx.x, lane = t & 31, wid = t >> 5;
  int wk = wid & 1, wq = wid >> 1;
  int r = lane >> 2, tq = lane & 3;
  int mat = blockIdx.z, kblk = blockIdx.x, qblk = blockIdx.y;
  int k0 = kblk * 128, q0 = qblk * 128;
  int qs = mat >> 1, ks = (mat == 1 || mat == 2) ? 1 : 0;
  const char* Ag = (const char*)&g_Khl[ks][k0][0];
  const char* Bg = (const char*)&g_Qhl[qs][q0][0];

  float acc[4][4][4];
#pragma unroll
  for (int i = 0; i < 4; i++)
#pragma unroll
    for (int j = 0; j < 4; j++)
#pragma unroll
      for (int v = 0; v < 4; v++) acc[i][j][v] = 0.f;

  {
    char* a = SM; char* b = SM + 10240;
#pragma unroll
    for (int i = 0; i < 2; i++) {
      int idx = t + 256 * i, row = idx >> 2, c16 = idx & 3;
      cp16(smem_u32(a + row * 80 + c16 * 16), Ag + (size_t)row * 384 + c16 * 16);
      cp16(smem_u32(b + row * 80 + c16 * 16), Bg + (size_t)row * 384 + c16 * 16);
    }
    CP_COMMIT();
  }
  for (int ch = 0; ch < 6; ch++) {
    if (ch < 5) {
      char* a = SM + ((ch + 1) & 1) * BUFSZ; char* b = a + 10240;
#pragma unroll
      for (int i = 0; i < 2; i++) {
        int idx = t + 256 * i, row = idx >> 2, c16 = idx & 3;
        cp16(smem_u32(a + row * 80 + c16 * 16), Ag + (size_t)row * 384 + (ch + 1) * 64 + c16 * 16);
        cp16(smem_u32(b + row * 80 + c16 * 16), Bg + (size_t)row * 384 + (ch + 1) * 64 + c16 * 16);
      }
      CP_COMMIT();
      CP_WAIT(1);
    } else {
      CP_WAIT(0);
    }
    __syncthreads();
    const uint32_t* As = (const uint32_t*)(SM + (ch & 1) * BUFSZ);
    const uint32_t* Bs = (const uint32_t*)(SM + (ch & 1) * BUFSZ + 10240);
#pragma unroll
    for (int s16 = 0; s16 < 2; s16++) {
      int f = s16 * 16;
      uint32_t a[4][4], b[4][2];
#pragma unroll
      for (int kf = 0; kf < 4; kf++) {
        int row = wk * 64 + kf * 16 + r;
        a[kf][0] = As[(row * SA + f + 2 * tq) >> 1];
        a[kf][1] = As[((row + 8) * SA + f + 2 * tq) >> 1];
        a[kf][2] = As[(row * SA + f + 2 * tq + 8) >> 1];
        a[kf][3] = As[((row + 8) * SA + f + 2 * tq + 8) >> 1];
      }
#pragma unroll
      for (int qf = 0; qf < 4; qf++) {
        int qr = wq * 32 + qf * 8 + r;
        b[qf][0] = Bs[(qr * SA + f + 2 * tq) >> 1];
        b[qf][1] = Bs[(qr * SA + f + 2 * tq + 8) >> 1];
      }
#pragma unroll
      for (int kf = 0; kf < 4; kf++)
#pragma unroll
        for (int qf = 0; qf < 4; qf++)
          mma16816(acc[kf][qf], a[kf][0], a[kf][1], a[kf][2], a[kf][3], b[qf][0], b[qf][1]);
    }
    __syncthreads();
  }

#pragma unroll
  for (int kf = 0; kf < 4; kf++)
#pragma unroll
    for (int qf = 0; qf < 4; qf++)
#pragma unroll
      for (int v = 0; v < 4; v++) acc[kf][qf][v] = __expf(acc[kf][qf][v]);

  float colp[4][2];
#pragma unroll
  for (int qf = 0; qf < 4; qf++) {
    colp[qf][0] = colp[qf][1] = 0.f;
#pragma unroll
    for (int kf = 0; kf < 4; kf++) {
      colp[qf][0] += acc[kf][qf][0] + acc[kf][qf][2];
      colp[qf][1] += acc[kf][qf][1] + acc[kf][qf][3];
    }
    colp[qf][0] += __shfl_xor_sync(0xffffffffu, colp[qf][0], 4);
    colp[qf][0] += __shfl_xor_sync(0xffffffffu, colp[qf][0], 8);
    colp[qf][0] += __shfl_xor_sync(0xffffffffu, colp[qf][0], 16);
    colp[qf][1] += __shfl_xor_sync(0xffffffffu, colp[qf][1], 4);
    colp[qf][1] += __shfl_xor_sync(0xffffffffu, colp[qf][1], 8);
    colp[qf][1] += __shfl_xor_sync(0xffffffffu, colp[qf][1], 16);
  }
  float* colsum = (float*)(SM + 35840);  // [2][128]
  if (lane < 4) {
#pragma unroll
    for (int qf = 0; qf < 4; qf++) {
      colsum[wk * 128 + wq * 32 + qf * 8 + 2 * tq + 0] = colp[qf][0];
      colsum[wk * 128 + wq * 32 + qf * 8 + 2 * tq + 1] = colp[qf][1];
    }
  }
  __syncthreads();
  if (t < 128) g_Prow[mat][kblk][q0 + t] = colsum[t] + colsum[128 + t];
}

// ---------------- K3a: reduce rowsum partials ----------------
__global__ void rowsum_kernel() {
  int id = blockIdx.x * 256 + threadIdx.x;
  int mat = id >> 12, m = id & 4095;
  float s = 0.f;
#pragma unroll
  for (int b = 0; b < 32; b++) s += g_Prow[mat][b][m];
  g_rs[mat][m] = 1.0f / s;
}
// ---------------- K3b: Vs = V * rs, bf16 hi only ----------------
__global__ void vscale_kernel() {
  int id = blockIdx.x * 256 + threadIdx.x;  // 4*64*2048
  int mat = id >> 17, rem = id & 131071;
  int c = rem >> 11, m = (rem & 2047) * 2;
  float v0 = g_V[mat >> 1][c * N + m] * g_rs[mat][m];
  float v1 = g_V[mat >> 1][c * N + m + 1] * g_rs[mat][m + 1];
  *(__nv_bfloat162*)&g_Vsb[mat][c * N + m] =
      __halves2bfloat162(__float2bfloat16(v0), __float2bfloat16(v1));
}

// ---------------- K4 (pass 2): fused logits-recompute + exp + MP ----------------
// CTA: output n-block (128 positions) x mat. K-tile resident (A, rows n).
// Iterate m-blocks: logits D[n][m] = K.Q^T (K=192), exp, stage bf16 [n][m],
// P[ch][n] += Vs[ch][m-blk] * E_stage. P accumulated in registers.
__global__ void __launch_bounds__(256) fused_mp() {
  extern __shared__ __align__(16) char SM[];
  char* Kres = SM;               // 128 x 400B (stride 200 bf16) = 51200
  char* Qb0 = SM + 51200;        // 51200 (E stage [n][m] stride 136 aliases here)
  char* Qb1 = SM + 102400;       // 51200
  char* Vb0 = SM + 153600;       // 64 x 272B = 17408
  char* Vb1 = SM + 171008;       // 17408  (total 188416)
  int t = threadIdx.x, lane = t & 31, wid = t >> 5;
  int r = lane >> 2, tq = lane & 3;
  int wn = wid & 1, wm = wid >> 1;    // logits: 64-n half, 32-m group
  int wc2 = wid & 1, wn2 = wid >> 1;  // MP: 32-ch half, 32-n group
  int nblk = blockIdx.x, mat = blockIdx.y;
  int n0 = nblk * 128;
  int qs = mat >> 1, ks = (mat == 1 || mat == 2) ? 1 : 0;
  const char* Kg = (const char*)&g_Khl[ks][n0][0];
  const char* Qg = (const char*)&g_Qhl[qs][0][0];
  const char* Vg = (const char*)&g_Vsb[mat][0];

  // K resident: 128 rows x 24 c16
#pragma unroll
  for (int i = 0; i < 12; i++) {
    int idx = t + 256 * i, row = idx / 24, c16 = idx % 24;
    cp16(smem_u32(Kres + row * 400 + c16 * 16), Kg + (size_t)row * 384 + c16 * 16);
  }
  CP_COMMIT();
  // Q(0), Vs(0)
#pragma unroll
  for (int i = 0; i < 12; i++) {
    int idx = t + 256 * i, row = idx / 24, c16 = idx % 24;
    cp16(smem_u32(Qb0 + row * 400 + c16 * 16), Qg + (size_t)row * 384 + c16 * 16);
  }
#pragma unroll
  for (int i = 0; i < 4; i++) {
    int idx = t + 256 * i, row = idx >> 4, c16 = idx & 15;
    cp16(smem_u32(Vb0 + row * 272 + c16 * 16), Vg + (size_t)row * 8192 + c16 * 16);
  }
  CP_COMMIT();

  float accP[2][4][4];
#pragma unroll
  for (int i = 0; i < 2; i++)
#pragma unroll
    for (int j = 0; j < 4; j++)
#pragma unroll
      for (int v = 0; v < 4; v++) accP[i][j][v] = 0.f;

  for (int it = 0; it < 32; it++) {
    char* Qc = (it & 1) ? Qb1 : Qb0;
    char* Vc = (it & 1) ? Vb1 : Vb0;
    __syncthreads();  // prior MP done reading stage/V before overwrite
    if (it + 1 < 32) {
      char* Qn = (it & 1) ? Qb0 : Qb1;
      char* Vn = (it & 1) ? Vb0 : Vb1;
      int m0 = (it + 1) * 128;
#pragma unroll
      for (int i = 0; i < 12; i++) {
        int idx = t + 256 * i, row = idx / 24, c16 = idx % 24;
        cp16(smem_u32(Qn + row * 400 + c16 * 16), Qg + (size_t)(m0 + row) * 384 + c16 * 16);
      }
#pragma unroll
      for (int i = 0; i < 4; i++) {
        int idx = t + 256 * i, row = idx >> 4, c16 = idx & 15;
        cp16(smem_u32(Vn + row * 272 + c16 * 16), Vg + ((size_t)row * N + m0) * 2 + c16 * 16);
      }
      CP_COMMIT();
      CP_WAIT(1);
    } else {
      CP_WAIT(0);
    }
    __syncthreads();

    // logits D[n][m]
    float acc[4][4][4];
#pragma unroll
    for (int i = 0; i < 4; i++)
#pragma unroll
      for (int j = 0; j < 4; j++)
#pragma unroll
        for (int v = 0; v < 4; v++) acc[i][j][v] = 0.f;
    {
      const uint32_t* As = (const uint32_t*)Kres;
      const uint32_t* Bs = (const uint32_t*)Qc;
#pragma unroll
      for (int kf = 0; kf < 12; kf++) {
        int f = kf * 16;
        uint32_t a[4][4], b[4][2];
#pragma unroll
        for (int nf = 0; nf < 4; nf++) {
          int row = wn * 64 + nf * 16 + r;
          a[nf][0] = As[row * 100 + f / 2 + tq];
          a[nf][1] = As[(row + 8) * 100 + f / 2 + tq];
          a[nf][2] = As[row * 100 + f / 2 + tq + 4];
          a[nf][3] = As[(row + 8) * 100 + f / 2 + tq + 4];
        }
#pragma unroll
        for (int mf = 0; mf < 4; mf++) {
          int mr = wm * 32 + mf * 8 + r;
          b[mf][0] = Bs[mr * 100 + f / 2 + tq];
          b[mf][1] = Bs[mr * 100 + f / 2 + tq + 4];
        }
#pragma unroll
        for (int nf = 0; nf < 4; nf++)
#pragma unroll
          for (int mf = 0; mf < 4; mf++)
            mma16816(acc[nf][mf], a[nf][0], a[nf][1], a[nf][2], a[nf][3], b[mf][0], b[mf][1]);
      }
    }
#pragma unroll
    for (int i = 0; i < 4; i++)
#pragma unroll
      for (int j = 0; j < 4; j++)
#pragma unroll
        for (int v = 0; v < 4; v++) acc[i][j][v] = __expf(acc[i][j][v]);
    __syncthreads();  // all warps done reading Qc fragments

    // stage E bf16 [n][m], stride 136, into Qc region
    {
      __nv_bfloat16* stg = (__nv_bfloat16*)Qc;
#pragma unroll
      for (int nf = 0; nf < 4; nf++)
#pragma unroll
        for (int mf = 0; mf < 4; mf++) {
          int n = wn * 64 + nf * 16 + r, m = wm * 32 + mf * 8 + 2 * tq;
          *(uint32_t*)&stg[n * 136 + m] = packbf(acc[nf][mf][0], acc[nf][mf][1]);
          *(uint32_t*)&stg[(n + 8) * 136 + m] = packbf(acc[nf][mf][2], acc[nf][mf][3]);
        }
    }
    __syncthreads();

    // MP: P[ch][n] += Vs[ch][m] * E[m][n]
    {
      const uint32_t* As2 = (const uint32_t*)Vc;
      const uint32_t* Bs2 = (const uint32_t*)Qc;
#pragma unroll
      for (int f2i = 0; f2i < 8; f2i++) {
        int f2 = f2i * 16;
        uint32_t a2[2][4], b2[4][2];
#pragma unroll
        for (int cf = 0; cf < 2; cf++) {
          int row = wc2 * 32 + cf * 16 + r;
          a2[cf][0] = As2[row * 68 + f2 / 2 + tq];
          a2[cf][1] = As2[(row + 8) * 68 + f2 / 2 + tq];
          a2[cf][2] = As2[row * 68 + f2 / 2 + tq + 4];
          a2[cf][3] = As2[(row + 8) * 68 + f2 / 2 + tq + 4];
        }
#pragma unroll
        for (int nf2 = 0; nf2 < 4; nf2++) {
          int nr = wn2 * 32 + nf2 * 8 + r;
          b2[nf2][0] = Bs2[nr * 68 + f2 / 2 + tq];
          b2[nf2][1] = Bs2[nr * 68 + f2 / 2 + tq + 4];
        }
#pragma unroll
        for (int cf = 0; cf < 2; cf++)
#pragma unroll
          for (int nf2 = 0; nf2 < 4; nf2++)
            mma16816(accP[cf][nf2], a2[cf][0], a2[cf][1], a2[cf][2], a2[cf][3],
                     b2[nf2][0], b2[nf2][1]);
      }
    }
  }

  // write P
#pragma unroll
  for (int cf = 0; cf < 2; cf++)
#pragma unroll
    for (int nf2 = 0; nf2 < 4; nf2++) {
      int ch = wc2 * 32 + cf * 16 + r, n = wn2 * 32 + nf2 * 8 + 2 * tq;
      *(float2*)&g_P[mat][ch * N + n0 + n] = make_float2(accP[cf][nf2][0], accP[cf][nf2][1]);
      *(float2*)&g_P[mat][(ch + 8) * N + n0 + n] = make_float2(accP[cf][nf2][2], accP[cf][nf2][3]);
    }
}

// ---------------- K5: Y = Wp * (P0 + P1 + X) ----------------
__global__ void __launch_bounds__(256) ygemm_kernel(
    const float* __restrict__ Xi, const float* __restrict__ Xj,
    const float* __restrict__ Wpi, const float* __restrict__ Wpj) {
  __shared__ float Ts[C][128];
  __shared__ float Wsm[C][C];
  int pair = blockIdx.y;
  const float* X = pair ? Xj : Xi;
  const float* Wp = pair ? Wpj : Wpi;
  int n0 = blockIdx.x * 128, t = threadIdx.x;
  for (int i = t; i < C * C / 4; i += 256)
    *(float4*)&Wsm[0][i * 4] = *(const float4*)&Wp[i * 4];
  for (int i = t; i < C * 32; i += 256) {
    int c = i >> 5, q = i & 31;
    float4 v = *(const float4*)&X[c * N + n0 + q * 4];
    float4 p0 = *(const float4*)&g_P[2 * pair][c * N + n0 + q * 4];
    float4 p1 = *(const float4*)&g_P[2 * pair + 1][c * N + n0 + q * 4];
    v.x += p0.x + p1.x; v.y += p0.y + p1.y; v.z += p0.z + p1.z; v.w += p0.w + p1.w;
    *(float4*)&Ts[c][q * 4] = v;
  }
  __syncthreads();
  int n = t & 127, h = t >> 7;
  float acc[32];
#pragma unroll
  for (int oo = 0; oo < 32; oo++) acc[oo] = 0.f;
  for (int c = 0; c < C; c++) {
    float x = Ts[c][n];
#pragma unroll
    for (int oo = 0; oo < 32; oo++) acc[oo] = fmaf(Wsm[h * 32 + oo][c], x, acc[oo]);
  }
#pragma unroll
  for (int oo = 0; oo < 32; oo++) g_Y[pair][(h * 32 + oo) * N + n0 + n] = acc[oo];
}

// ---------------- K6: BN stats ----------------
__global__ void bnstats_kernel() {
  int pair = blockIdx.x >> 6, c = blockIdx.x & 63;
  const float* y = &g_Y[pair][c * N];
  float s = 0.f, sq = 0.f;
  for (int n = threadIdx.x; n < N; n += 128) {
    float v = y[n];
    s += v; sq += v * v;
  }
  __shared__ float rs_[128], rq_[128];
  rs_[threadIdx.x] = s; rq_[threadIdx.x] = sq;
  __syncthreads();
  for (int off = 64; off > 0; off >>= 1) {
    if (threadIdx.x < off) {
      rs_[threadIdx.x] += rs_[threadIdx.x + off];
      rq_[threadIdx.x] += rq_[threadIdx.x + off];
    }
    __syncthreads();
  }
  if (threadIdx.x == 0) {
    float mean = rs_[0] * (1.0f / N);
    float var = rq_[0] * (1.0f / N) - mean * mean;
    g_bn[pair][0][c] = mean;
    g_bn[pair][1][c] = rsqrtf(var + 1e-5f);
  }
}

// ---------------- K7: BN + LeakyReLU + sum ----------------
__global__ void epilogue_kernel(const float* __restrict__ gi, const float* __restrict__ bi,
                                const float* __restrict__ gj, const float* __restrict__ bj,
                                float* __restrict__ out) {
  int id = blockIdx.x * 256 + threadIdx.x;
  int c = id >> 12;
  float yi = g_Y[0][id], yj = g_Y[1][id];
  float vi = (yi - g_bn[0][0][c]) * g_bn[0][1][c] * gi[c] + bi[c];
  float vj = (yj - g_bn[1][0][c]) * g_bn[1][1][c] * gj[c] + bj[c];
  vi = (vi >= 0.f) ? vi : 0.01f * vi;
  vj = (vj >= 0.f) ? vj : 0.01f * vj;
  out[id] = vi + vj;
}

// ---------------- launch ----------------
extern "C" void kernel_launch(void* const* d_in, const int* in_sizes, int n_in,
                              void* d_out, int out_size) {
  const float* Xi = (const float*)d_in[0];
  const float* Xj = (const float*)d_in[1];
  const float* Wq = (const float*)d_in[2];
  const float* Wk = (const float*)d_in[3];
  const float* Wv = (const float*)d_in[4];
  const float* Wpi = (const float*)d_in[5];
  const float* Wpj = (const float*)d_in[6];
  const float* gi = (const float*)d_in[7];
  const float* bi = (const float*)d_in[8];
  const float* gj = (const float*)d_in[9];
  const float* bj = (const float*)d_in[10];
  float* out = (float*)d_out;

  cudaFuncSetAttribute(fused_mp, cudaFuncAttributeMaxDynamicSharedMemorySize, 188416);

  qkv_kernel<<<dim3(32, 2), 256>>>(Xi, Xj, Wq, Wk, Wv);
  pass1_logits<<<dim3(32, 32, 4), 256>>>();
  rowsum_kernel<<<64, 256>>>();
  vscale_kernel<<<2048, 256>>>();
  fused_mp<<<dim3(32, 4), 256, 188416>>>();
  ygemm_kernel<<<dim3(32, 2), 256>>>(Xi, Xj, Wpi, Wpj);
  bnstats_kernel<<<128, 128>>>();
  epilogue_kernel<<<1024, 256>>>(gi, bi, gj, bj, out);
}

// round 8
// speedup vs baseline: 2.1241x; 1.1723x over previous
#include <cuda_runtime.h>
#include <cuda_bf16.h>
#include <cstdint>

#define N 4096
#define C 64

// ---------------- scratch (device globals; no allocation) ----------------
__device__ __align__(1024) __nv_bfloat16 g_Qhl[2][N][192];  // [q]: 0:64 Qh, 64:128 Ql, 128:192 Qh (scaled 1/8)
__device__ __align__(1024) __nv_bfloat16 g_Khl[2][N][192];  // [k]: 0:64 Kh, 64:128 Kh, 128:192 Kl
__device__ __align__(1024) __nv_bfloat16 g_Qh2[2][N][64];   // compact hi-only (scaled 1/8)
__device__ __align__(1024) __nv_bfloat16 g_Kh2[2][N][64];   // compact hi-only
__device__ __align__(1024) float g_V[2][C * N];
__device__ __align__(1024) __nv_bfloat16 g_Vsb[4][C * N];   // V * (1/rowsum), bf16 hi only
__device__ float g_Prow[4][32][N];   // per-kblk partial sums (per query m)
__device__ __align__(1024) float g_P[4][C * N];  // message-passing output per mat
__device__ float g_Y[2][C * N];
__device__ float g_bn[2][2][C];

// ---------------- helpers ----------------
__device__ __forceinline__ uint32_t smem_u32(const void* p) {
  uint32_t a;
  asm("{ .reg .u64 t; cvta.to.shared.u64 t, %1; cvt.u32.u64 %0, t; }" : "=r"(a) : "l"(p));
  return a;
}
__device__ __forceinline__ void cp16(uint32_t dst, const void* src) {
  asm volatile("cp.async.cg.shared.global [%0], [%1], 16;" :: "r"(dst), "l"(src) : "memory");
}
#define CP_COMMIT() asm volatile("cp.async.commit_group;" ::: "memory")
#define CP_WAIT(n_) asm volatile("cp.async.wait_group %0;" :: "n"(n_) : "memory")

__device__ __forceinline__ void mma16816(float* c, uint32_t a0, uint32_t a1, uint32_t a2,
                                         uint32_t a3, uint32_t b0, uint32_t b1) {
  asm volatile(
      "mma.sync.aligned.m16n8k16.row.col.f32.bf16.bf16.f32 "
      "{%0,%1,%2,%3}, {%4,%5,%6,%7}, {%8,%9}, {%0,%1,%2,%3};"
      : "+f"(c[0]), "+f"(c[1]), "+f"(c[2]), "+f"(c[3])
      : "r"(a0), "r"(a1), "r"(a2), "r"(a3), "r"(b0), "r"(b1));
}
__device__ __forceinline__ uint32_t packbf(float x, float y) {
  __nv_bfloat162 p = __halves2bfloat162(__float2bfloat16(x), __float2bfloat16(y));
  return *(uint32_t*)&p;
}

#define SA 40           // pass-1 smem chunk row stride in bf16 (80B)
#define BUFSZ 20480

// ---------------- K1: QKV projections (fp32 -> bf16 hi/lo + compact hi) ----------------
__global__ void __launch_bounds__(256) qkv_kernel(
    const float* __restrict__ Xi, const float* __restrict__ Xj,
    const float* __restrict__ Wq, const float* __restrict__ Wk, const float* __restrict__ Wv) {
  __shared__ float Xs[C][128];
  int side = blockIdx.y;
  const float* X = side ? Xj : Xi;
  int n0 = blockIdx.x * 128, t = threadIdx.x;
  for (int i = t; i < C * 32; i += 256) {
    int c = i >> 5, q = i & 31;
    *(float4*)&Xs[c][q * 4] = *(const float4*)&X[c * N + n0 + q * 4];
  }
  __syncthreads();
  int o = t & 63, g = t >> 6;
  float acc[32];
  {  // Q (scaled 1/8)
#pragma unroll
    for (int k = 0; k < 32; k++) acc[k] = 0.f;
    for (int c = 0; c < C; c++) {
      float w = __ldg(&Wq[o * C + c]);
#pragma unroll
      for (int k = 0; k < 32; k++) acc[k] = fmaf(w, Xs[c][g + 4 * k], acc[k]);
    }
#pragma unroll
    for (int k = 0; k < 32; k++) {
      float v = acc[k] * 0.125f;
      __nv_bfloat16 h = __float2bfloat16(v);
      __nv_bfloat16 L = __float2bfloat16(v - __bfloat162float(h));
      int n = n0 + g + 4 * k;
      g_Qhl[side][n][o] = h; g_Qhl[side][n][64 + o] = L; g_Qhl[side][n][128 + o] = h;
      g_Qh2[side][n][o] = h;
    }
  }
  {  // K
#pragma unroll
    for (int k = 0; k < 32; k++) acc[k] = 0.f;
    for (int c = 0; c < C; c++) {
      float w = __ldg(&Wk[o * C + c]);
#pragma unroll
      for (int k = 0; k < 32; k++) acc[k] = fmaf(w, Xs[c][g + 4 * k], acc[k]);
    }
#pragma unroll
    for (int k = 0; k < 32; k++) {
      float v = acc[k];
      __nv_bfloat16 h = __float2bfloat16(v);
      __nv_bfloat16 L = __float2bfloat16(v - __bfloat162float(h));
      int n = n0 + g + 4 * k;
      g_Khl[side][n][o] = h; g_Khl[side][n][64 + o] = h; g_Khl[side][n][128 + o] = L;
      g_Kh2[side][n][o] = h;
    }
  }
  {  // V fp32
#pragma unroll
    for (int k = 0; k < 32; k++) acc[k] = 0.f;
    for (int c = 0; c < C; c++) {
      float w = __ldg(&Wv[o * C + c]);
#pragma unroll
      for (int k = 0; k < 32; k++) acc[k] = fmaf(w, Xs[c][g + 4 * k], acc[k]);
    }
#pragma unroll
    for (int k = 0; k < 32; k++) g_V[side][o * N + n0 + g + 4 * k] = acc[k];
  }
}

// ---------------- K2 (pass 1): logits K=192 + exp + rowsum partials ----------------
__global__ void __launch_bounds__(256) pass1_logits() {
  __shared__ __align__(16) char SM[2 * BUFSZ];
  int t = threadIdx.x, lane = t & 31, wid = t >> 5;
  int wk = wid & 1, wq = wid >> 1;
  int r = lane >> 2, tq = lane & 3;
  int mat = blockIdx.z, kblk = blockIdx.x, qblk = blockIdx.y;
  int k0 = kblk * 128, q0 = qblk * 128;
  int qs = mat >> 1, ks = (mat == 1 || mat == 2) ? 1 : 0;
  const char* Ag = (const char*)&g_Khl[ks][k0][0];
  const char* Bg = (const char*)&g_Qhl[qs][q0][0];

  float acc[4][4][4];
#pragma unroll
  for (int i = 0; i < 4; i++)
#pragma unroll
    for (int j = 0; j < 4; j++)
#pragma unroll
      for (int v = 0; v < 4; v++) acc[i][j][v] = 0.f;

  {
    char* a = SM; char* b = SM + 10240;
#pragma unroll
    for (int i = 0; i < 2; i++) {
      int idx = t + 256 * i, row = idx >> 2, c16 = idx & 3;
      cp16(smem_u32(a + row * 80 + c16 * 16), Ag + (size_t)row * 384 + c16 * 16);
      cp16(smem_u32(b + row * 80 + c16 * 16), Bg + (size_t)row * 384 + c16 * 16);
    }
    CP_COMMIT();
  }
  for (int ch = 0; ch < 6; ch++) {
    if (ch < 5) {
      char* a = SM + ((ch + 1) & 1) * BUFSZ; char* b = a + 10240;
#pragma unroll
      for (int i = 0; i < 2; i++) {
        int idx = t + 256 * i, row = idx >> 2, c16 = idx & 3;
        cp16(smem_u32(a + row * 80 + c16 * 16), Ag + (size_t)row * 384 + (ch + 1) * 64 + c16 * 16);
        cp16(smem_u32(b + row * 80 + c16 * 16), Bg + (size_t)row * 384 + (ch + 1) * 64 + c16 * 16);
      }
      CP_COMMIT();
      CP_WAIT(1);
    } else {
      CP_WAIT(0);
    }
    __syncthreads();
    const uint32_t* As = (const uint32_t*)(SM + (ch & 1) * BUFSZ);
    const uint32_t* Bs = (const uint32_t*)(SM + (ch & 1) * BUFSZ + 10240);
#pragma unroll
    for (int s16 = 0; s16 < 2; s16++) {
      int f = s16 * 16;
      uint32_t a[4][4], b[4][2];
#pragma unroll
      for (int kf = 0; kf < 4; kf++) {
        int row = wk * 64 + kf * 16 + r;
        a[kf][0] = As[(row * SA + f + 2 * tq) >> 1];
        a[kf][1] = As[((row + 8) * SA + f + 2 * tq) >> 1];
        a[kf][2] = As[(row * SA + f + 2 * tq + 8) >> 1];
        a[kf][3] = As[((row + 8) * SA + f + 2 * tq + 8) >> 1];
      }
#pragma unroll
      for (int qf = 0; qf < 4; qf++) {
        int qr = wq * 32 + qf * 8 + r;
        b[qf][0] = Bs[(qr * SA + f + 2 * tq) >> 1];
        b[qf][1] = Bs[(qr * SA + f + 2 * tq + 8) >> 1];
      }
#pragma unroll
      for (int kf = 0; kf < 4; kf++)
#pragma unroll
        for (int qf = 0; qf < 4; qf++)
          mma16816(acc[kf][qf], a[kf][0], a[kf][1], a[kf][2], a[kf][3], b[qf][0], b[qf][1]);
    }
    __syncthreads();
  }

#pragma unroll
  for (int kf = 0; kf < 4; kf++)
#pragma unroll
    for (int qf = 0; qf < 4; qf++)
#pragma unroll
      for (int v = 0; v < 4; v++) acc[kf][qf][v] = __expf(acc[kf][qf][v]);

  float colp[4][2];
#pragma unroll
  for (int qf = 0; qf < 4; qf++) {
    colp[qf][0] = colp[qf][1] = 0.f;
#pragma unroll
    for (int kf = 0; kf < 4; kf++) {
      colp[qf][0] += acc[kf][qf][0] + acc[kf][qf][2];
      colp[qf][1] += acc[kf][qf][1] + acc[kf][qf][3];
    }
    colp[qf][0] += __shfl_xor_sync(0xffffffffu, colp[qf][0], 4);
    colp[qf][0] += __shfl_xor_sync(0xffffffffu, colp[qf][0], 8);
    colp[qf][0] += __shfl_xor_sync(0xffffffffu, colp[qf][0], 16);
    colp[qf][1] += __shfl_xor_sync(0xffffffffu, colp[qf][1], 4);
    colp[qf][1] += __shfl_xor_sync(0xffffffffu, colp[qf][1], 8);
    colp[qf][1] += __shfl_xor_sync(0xffffffffu, colp[qf][1], 16);
  }
  float* colsum = (float*)(SM + 35840);
  if (lane < 4) {
#pragma unroll
    for (int qf = 0; qf < 4; qf++) {
      colsum[wk * 128 + wq * 32 + qf * 8 + 2 * tq + 0] = colp[qf][0];
      colsum[wk * 128 + wq * 32 + qf * 8 + 2 * tq + 1] = colp[qf][1];
    }
  }
  __syncthreads();
  if (t < 128) g_Prow[mat][kblk][q0 + t] = colsum[t] + colsum[128 + t];
}

// ---------------- K3: fused rowsum-reduce + V scale (bf16) ----------------
__global__ void __launch_bounds__(256) rsvscale_kernel() {
  __shared__ float rs_s[128];
  int mat = blockIdx.x >> 5, m0 = (blockIdx.x & 31) * 128;
  int t = threadIdx.x;
  if (t < 128) {
    float s = 0.f;
#pragma unroll
    for (int b = 0; b < 32; b++) s += g_Prow[mat][b][m0 + t];
    rs_s[t] = 1.0f / s;
  }
  __syncthreads();
  int c = t >> 2, g = t & 3;  // channel, m-group of 32
  const float* Vp = &g_V[mat >> 1][c * N + m0 + g * 32];
  __nv_bfloat16* Op = &g_Vsb[mat][c * N + m0 + g * 32];
#pragma unroll
  for (int k = 0; k < 16; k++) {
    float v0 = Vp[2 * k] * rs_s[g * 32 + 2 * k];
    float v1 = Vp[2 * k + 1] * rs_s[g * 32 + 2 * k + 1];
    *(__nv_bfloat162*)&Op[2 * k] = __halves2bfloat162(__float2bfloat16(v0), __float2bfloat16(v1));
  }
}

// ---------------- K4 (pass 2): fused K=64 logits-recompute + exp + MP ----------------
__global__ void __launch_bounds__(256) fused_mp() {
  extern __shared__ __align__(16) char SM[];
  char* Kres = SM;                      // 128 x 144B = 18432
  char* Qb = SM + 18432;                // 3 x 18432 = 55296
  char* Vb = SM + 18432 + 55296;        // 3 x 17408 = 52224
  char* Stg = SM + 18432 + 55296 + 52224;  // 128 x 272B = 34816 (total 160768)
  int t = threadIdx.x, lane = t & 31, wid = t >> 5;
  int r = lane >> 2, tq = lane & 3;
  int wn = wid & 1, wm = wid >> 1;    // logits: n half (64), m group (32)
  int wc2 = wid & 1, wn2 = wid >> 1;  // MP: ch half (32), n group (32)
  int nblk = blockIdx.x, mat = blockIdx.y;
  int n0 = nblk * 128;
  int qs = mat >> 1, ks = (mat == 1 || mat == 2) ? 1 : 0;
  const char* Kg = (const char*)&g_Kh2[ks][n0][0];
  const char* Qg = (const char*)&g_Qh2[qs][0][0];
  const char* Vg = (const char*)&g_Vsb[mat][0];

  // K resident: 128 rows x 8 c16
#pragma unroll
  for (int i = 0; i < 4; i++) {
    int idx = t + 256 * i, row = idx >> 3, c16 = idx & 7;
    cp16(smem_u32(Kres + row * 144 + c16 * 16), Kg + (size_t)row * 128 + c16 * 16);
  }
  CP_COMMIT();
  // prologue: Q/V chunks 0 and 1 (V rows are 256B: 16 c16 chunks!)
#pragma unroll
  for (int p = 0; p < 2; p++) {
    char* q = Qb + p * 18432;
    char* v = Vb + p * 17408;
    int m0 = p * 128;
#pragma unroll
    for (int i = 0; i < 4; i++) {
      int idx = t + 256 * i, row = idx >> 3, c16 = idx & 7;
      cp16(smem_u32(q + row * 144 + c16 * 16), Qg + (size_t)(m0 + row) * 128 + c16 * 16);
    }
#pragma unroll
    for (int i = 0; i < 4; i++) {
      int idx = t + 256 * i, row = idx >> 4, c16 = idx & 15;
      cp16(smem_u32(v + row * 272 + c16 * 16), Vg + ((size_t)row * N + m0) * 2 + c16 * 16);
    }
    CP_COMMIT();
  }

  float accP[2][4][4];
#pragma unroll
  for (int i = 0; i < 2; i++)
#pragma unroll
    for (int j = 0; j < 4; j++)
#pragma unroll
      for (int v = 0; v < 4; v++) accP[i][j][v] = 0.f;

  for (int it = 0; it < 32; it++) {
    if (it == 31) { CP_WAIT(0); } else { CP_WAIT(1); }
    __syncthreads();  // chunk(it) visible; all warps past MP(it-1)

    const uint32_t* As = (const uint32_t*)Kres;
    const uint32_t* Bs = (const uint32_t*)(Qb + (it % 3) * 18432);
    float acc[4][4][4];
#pragma unroll
    for (int i = 0; i < 4; i++)
#pragma unroll
      for (int j = 0; j < 4; j++)
#pragma unroll
        for (int v = 0; v < 4; v++) acc[i][j][v] = 0.f;
#pragma unroll
    for (int kf = 0; kf < 4; kf++) {
      int fo = kf * 8;  // f/2
      uint32_t a[4][4], b[4][2];
#pragma unroll
      for (int nf = 0; nf < 4; nf++) {
        int row = wn * 64 + nf * 16 + r;
        a[nf][0] = As[row * 36 + fo + tq];
        a[nf][1] = As[(row + 8) * 36 + fo + tq];
        a[nf][2] = As[row * 36 + fo + tq + 4];
        a[nf][3] = As[(row + 8) * 36 + fo + tq + 4];
      }
#pragma unroll
      for (int mf = 0; mf < 4; mf++) {
        int mr = wm * 32 + mf * 8 + r;
        b[mf][0] = Bs[mr * 36 + fo + tq];
        b[mf][1] = Bs[mr * 36 + fo + tq + 4];
      }
#pragma unroll
      for (int nf = 0; nf < 4; nf++)
#pragma unroll
        for (int mf = 0; mf < 4; mf++)
          mma16816(acc[nf][mf], a[nf][0], a[nf][1], a[nf][2], a[nf][3], b[mf][0], b[mf][1]);
    }
#pragma unroll
    for (int i = 0; i < 4; i++)
#pragma unroll
      for (int j = 0; j < 4; j++)
#pragma unroll
        for (int v = 0; v < 4; v++) acc[i][j][v] = __expf(acc[i][j][v]);

    // stage E bf16 [n][m] stride 136
    {
      __nv_bfloat16* stg = (__nv_bfloat16*)Stg;
#pragma unroll
      for (int nf = 0; nf < 4; nf++)
#pragma unroll
        for (int mf = 0; mf < 4; mf++) {
          int n = wn * 64 + nf * 16 + r, m = wm * 32 + mf * 8 + 2 * tq;
          *(uint32_t*)&stg[n * 136 + m] = packbf(acc[nf][mf][0], acc[nf][mf][1]);
          *(uint32_t*)&stg[(n + 8) * 136 + m] = packbf(acc[nf][mf][2], acc[nf][mf][3]);
        }
    }
    __syncthreads();  // stage visible

    // MP: P[ch][n] += Vs[ch][m] * E[m][n]
    {
      const uint32_t* As2 = (const uint32_t*)(Vb + (it % 3) * 17408);
      const uint32_t* Bs2 = (const uint32_t*)Stg;
#pragma unroll
      for (int f2i = 0; f2i < 8; f2i++) {
        int fo = f2i * 8;
        uint32_t a2[2][4], b2[4][2];
#pragma unroll
        for (int cf = 0; cf < 2; cf++) {
          int row = wc2 * 32 + cf * 16 + r;
          a2[cf][0] = As2[row * 68 + fo + tq];
          a2[cf][1] = As2[(row + 8) * 68 + fo + tq];
          a2[cf][2] = As2[row * 68 + fo + tq + 4];
          a2[cf][3] = As2[(row + 8) * 68 + fo + tq + 4];
        }
#pragma unroll
        for (int nf2 = 0; nf2 < 4; nf2++) {
          int nr = wn2 * 32 + nf2 * 8 + r;
          b2[nf2][0] = Bs2[nr * 68 + fo + tq];
          b2[nf2][1] = Bs2[nr * 68 + fo + tq + 4];
        }
#pragma unroll
        for (int cf = 0; cf < 2; cf++)
#pragma unroll
          for (int nf2 = 0; nf2 < 4; nf2++)
            mma16816(accP[cf][nf2], a2[cf][0], a2[cf][1], a2[cf][2], a2[cf][3],
                     b2[nf2][0], b2[nf2][1]);
      }
    }
    // prefetch chunk it+2 into buffer (it+2)%3
    if (it + 2 < 32) {
      char* q = Qb + ((it + 2) % 3) * 18432;
      char* v = Vb + ((it + 2) % 3) * 17408;
      int m0 = (it + 2) * 128;
#pragma unroll
      for (int i = 0; i < 4; i++) {
        int idx = t + 256 * i, row = idx >> 3, c16 = idx & 7;
        cp16(smem_u32(q + row * 144 + c16 * 16), Qg + (size_t)(m0 + row) * 128 + c16 * 16);
      }
#pragma unroll
      for (int i = 0; i < 4; i++) {
        int idx = t + 256 * i, row = idx >> 4, c16 = idx & 15;
        cp16(smem_u32(v + row * 272 + c16 * 16), Vg + ((size_t)row * N + m0) * 2 + c16 * 16);
      }
      CP_COMMIT();
    }
  }

  // write P
#pragma unroll
  for (int cf = 0; cf < 2; cf++)
#pragma unroll
    for (int nf2 = 0; nf2 < 4; nf2++) {
      int ch = wc2 * 32 + cf * 16 + r, n = wn2 * 32 + nf2 * 8 + 2 * tq;
      *(float2*)&g_P[mat][ch * N + n0 + n] = make_float2(accP[cf][nf2][0], accP[cf][nf2][1]);
      *(float2*)&g_P[mat][(ch + 8) * N + n0 + n] = make_float2(accP[cf][nf2][2], accP[cf][nf2][3]);
    }
}

// ---------------- K5: Y = Wp * (P0 + P1 + X) ----------------
__global__ void __launch_bounds__(256) ygemm_kernel(
    const float* __restrict__ Xi, const float* __restrict__ Xj,
    const float* __restrict__ Wpi, const float* __restrict__ Wpj) {
  __shared__ float Ts[C][128];
  __shared__ float Wsm[C][C];
  int pair = blockIdx.y;
  const float* X = pair ? Xj : Xi;
  const float* Wp = pair ? Wpj : Wpi;
  int n0 = blockIdx.x * 128, t = threadIdx.x;
  for (int i = t; i < C * C / 4; i += 256)
    *(float4*)&Wsm[0][i * 4] = *(const float4*)&Wp[i * 4];
  for (int i = t; i < C * 32; i += 256) {
    int c = i >> 5, q = i & 31;
    float4 v = *(const float4*)&X[c * N + n0 + q * 4];
    float4 p0 = *(const float4*)&g_P[2 * pair][c * N + n0 + q * 4];
    float4 p1 = *(const float4*)&g_P[2 * pair + 1][c * N + n0 + q * 4];
    v.x += p0.x + p1.x; v.y += p0.y + p1.y; v.z += p0.z + p1.z; v.w += p0.w + p1.w;
    *(float4*)&Ts[c][q * 4] = v;
  }
  __syncthreads();
  int n = t & 127, h = t >> 7;
  float acc[32];
#pragma unroll
  for (int oo = 0; oo < 32; oo++) acc[oo] = 0.f;
  for (int c = 0; c < C; c++) {
    float x = Ts[c][n];
#pragma unroll
    for (int oo = 0; oo < 32; oo++) acc[oo] = fmaf(Wsm[h * 32 + oo][c], x, acc[oo]);
  }
#pragma unroll
  for (int oo = 0; oo < 32; oo++) g_Y[pair][(h * 32 + oo) * N + n0 + n] = acc[oo];
}

// ---------------- K6: BN stats ----------------
__global__ void bnstats_kernel() {
  int pair = blockIdx.x >> 6, c = blockIdx.x & 63;
  const float* y = &g_Y[pair][c * N];
  float s = 0.f, sq = 0.f;
  for (int n = threadIdx.x; n < N; n += 128) {
    float v = y[n];
    s += v; sq += v * v;
  }
  __shared__ float rs_[128], rq_[128];
  rs_[threadIdx.x] = s; rq_[threadIdx.x] = sq;
  __syncthreads();
  for (int off = 64; off > 0; off >>= 1) {
    if (threadIdx.x < off) {
      rs_[threadIdx.x] += rs_[threadIdx.x + off];
      rq_[threadIdx.x] += rq_[threadIdx.x + off];
    }
    __syncthreads();
  }
  if (threadIdx.x == 0) {
    float mean = rs_[0] * (1.0f / N);
    float var = rq_[0] * (1.0f / N) - mean * mean;
    g_bn[pair][0][c] = mean;
    g_bn[pair][1][c] = rsqrtf(var + 1e-5f);
  }
}

// ---------------- K7: BN + LeakyReLU + sum ----------------
__global__ void epilogue_kernel(const float* __restrict__ gi, const float* __restrict__ bi,
                                const float* __restrict__ gj, const float* __restrict__ bj,
                                float* __restrict__ out) {
  int id = blockIdx.x * 256 + threadIdx.x;
  int c = id >> 12;
  float yi = g_Y[0][id], yj = g_Y[1][id];
  float vi = (yi - g_bn[0][0][c]) * g_bn[0][1][c] * gi[c] + bi[c];
  float vj = (yj - g_bn[1][0][c]) * g_bn[1][1][c] * gj[c] + bj[c];
  vi = (vi >= 0.f) ? vi : 0.01f * vi;
  vj = (vj >= 0.f) ? vj : 0.01f * vj;
  out[id] = vi + vj;
}

// ---------------- launch ----------------
extern "C" void kernel_launch(void* const* d_in, const int* in_sizes, int n_in,
                              void* d_out, int out_size) {
  const float* Xi = (const float*)d_in[0];
  const float* Xj = (const float*)d_in[1];
  const float* Wq = (const float*)d_in[2];
  const float* Wk = (const float*)d_in[3];
  const float* Wv = (const float*)d_in[4];
  const float* Wpi = (const float*)d_in[5];
  const float* Wpj = (const float*)d_in[6];
  const float* gi = (const float*)d_in[7];
  const float* bi = (const float*)d_in[8];
  const float* gj = (const float*)d_in[9];
  const float* bj = (const float*)d_in[10];
  float* out = (float*)d_out;

  cudaFuncSetAttribute(fused_mp, cudaFuncAttributeMaxDynamicSharedMemorySize, 160768);

  qkv_kernel<<<dim3(32, 2), 256>>>(Xi, Xj, Wq, Wk, Wv);
  pass1_logits<<<dim3(32, 32, 4), 256>>>();
  rsvscale_kernel<<<128, 256>>>();
  fused_mp<<<dim3(32, 4), 256, 160768>>>();
  ygemm_kernel<<<dim3(32, 2), 256>>>(Xi, Xj, Wpi, Wpj);
  bnstats_kernel<<<128, 128>>>();
  epilogue_kernel<<<1024, 256>>>(gi, bi, gj, bj, out);
}

// round 9
// speedup vs baseline: 3.1560x; 1.4858x over previous
#include <cuda_runtime.h>
#include <cuda_bf16.h>
#include <cstdint>

#define N 4096
#define C 64

// ---------------- scratch (device globals; no allocation) ----------------
__device__ __align__(1024) __nv_bfloat16 g_Qh2[2][N][64];   // hi-only, scaled 1/8, [q][c]
__device__ __align__(1024) __nv_bfloat16 g_Kh2[2][N][64];   // hi-only, [k][c]
__device__ __align__(1024) float g_V[2][C * N];
__device__ __align__(1024) __nv_bfloat16 g_Vsb[4][C * N];   // V * (1/rowsum), bf16
__device__ float g_Prow[4][32][N];   // per-kblk partial sums (per query m)
__device__ __align__(1024) float g_P[4][C * N];  // message-passing output per mat
__device__ float g_Y[2][C * N];
__device__ float g_bn[2][2][C];

// ---------------- helpers ----------------
__device__ __forceinline__ uint32_t smem_u32(const void* p) {
  uint32_t a;
  asm("{ .reg .u64 t; cvta.to.shared.u64 t, %1; cvt.u32.u64 %0, t; }" : "=r"(a) : "l"(p));
  return a;
}
__device__ __forceinline__ void cp16(uint32_t dst, const void* src) {
  asm volatile("cp.async.cg.shared.global [%0], [%1], 16;" :: "r"(dst), "l"(src) : "memory");
}
#define CP_COMMIT() asm volatile("cp.async.commit_group;" ::: "memory")
#define CP_WAIT(n_) asm volatile("cp.async.wait_group %0;" :: "n"(n_) : "memory")

__device__ __forceinline__ void mma16816(float* c, uint32_t a0, uint32_t a1, uint32_t a2,
                                         uint32_t a3, uint32_t b0, uint32_t b1) {
  asm volatile(
      "mma.sync.aligned.m16n8k16.row.col.f32.bf16.bf16.f32 "
      "{%0,%1,%2,%3}, {%4,%5,%6,%7}, {%8,%9}, {%0,%1,%2,%3};"
      : "+f"(c[0]), "+f"(c[1]), "+f"(c[2]), "+f"(c[3])
      : "r"(a0), "r"(a1), "r"(a2), "r"(a3), "r"(b0), "r"(b1));
}
__device__ __forceinline__ uint32_t packbf(float x, float y) {
  __nv_bfloat162 p = __halves2bfloat162(__float2bfloat16(x), __float2bfloat16(y));
  return *(uint32_t*)&p;
}

// ---------------- K1: QKV projections (fp32 -> bf16 hi) ----------------
__global__ void __launch_bounds__(256) qkv_kernel(
    const float* __restrict__ Xi, const float* __restrict__ Xj,
    const float* __restrict__ Wq, const float* __restrict__ Wk, const float* __restrict__ Wv) {
  __shared__ float Xs[C][128];
  int side = blockIdx.y;
  const float* X = side ? Xj : Xi;
  int n0 = blockIdx.x * 128, t = threadIdx.x;
  for (int i = t; i < C * 32; i += 256) {
    int c = i >> 5, q = i & 31;
    *(float4*)&Xs[c][q * 4] = *(const float4*)&X[c * N + n0 + q * 4];
  }
  __syncthreads();
  int o = t & 63, g = t >> 6;
  float acc[32];
  {  // Q (scaled 1/8)
#pragma unroll
    for (int k = 0; k < 32; k++) acc[k] = 0.f;
    for (int c = 0; c < C; c++) {
      float w = __ldg(&Wq[o * C + c]);
#pragma unroll
      for (int k = 0; k < 32; k++) acc[k] = fmaf(w, Xs[c][g + 4 * k], acc[k]);
    }
#pragma unroll
    for (int k = 0; k < 32; k++)
      g_Qh2[side][n0 + g + 4 * k][o] = __float2bfloat16(acc[k] * 0.125f);
  }
  {  // K
#pragma unroll
    for (int k = 0; k < 32; k++) acc[k] = 0.f;
    for (int c = 0; c < C; c++) {
      float w = __ldg(&Wk[o * C + c]);
#pragma unroll
      for (int k = 0; k < 32; k++) acc[k] = fmaf(w, Xs[c][g + 4 * k], acc[k]);
    }
#pragma unroll
    for (int k = 0; k < 32; k++)
      g_Kh2[side][n0 + g + 4 * k][o] = __float2bfloat16(acc[k]);
  }
  {  // V fp32
#pragma unroll
    for (int k = 0; k < 32; k++) acc[k] = 0.f;
    for (int c = 0; c < C; c++) {
      float w = __ldg(&Wv[o * C + c]);
#pragma unroll
      for (int k = 0; k < 32; k++) acc[k] = fmaf(w, Xs[c][g + 4 * k], acc[k]);
    }
#pragma unroll
    for (int k = 0; k < 32; k++) g_V[side][o * N + n0 + g + 4 * k] = acc[k];
  }
}

// ---------------- K2 (pass 1): K=64 logits + exp + rowsum partials ----------------
// mat 0:(Qi,Ki) 1:(Qi,Kj) 2:(Qj,Kj) 3:(Qj,Ki); D[k][q]; s[q] = sum over k
__global__ void __launch_bounds__(256) pass1_logits() {
  __shared__ __align__(16) char SM[36864 + 1024];
  int t = threadIdx.x, lane = t & 31, wid = t >> 5;
  int wk = wid & 1, wq = wid >> 1;
  int r = lane >> 2, tq = lane & 3;
  int mat = blockIdx.z, kblk = blockIdx.x, qblk = blockIdx.y;
  int k0 = kblk * 128, q0 = qblk * 128;
  int qs = mat >> 1, ks = (mat == 1 || mat == 2) ? 1 : 0;
  const char* Ag = (const char*)&g_Kh2[ks][k0][0];
  const char* Bg = (const char*)&g_Qh2[qs][q0][0];
  char* Asm_ = SM;            // 128 x 144B
  char* Bsm_ = SM + 18432;    // 128 x 144B

#pragma unroll
  for (int i = 0; i < 4; i++) {
    int idx = t + 256 * i, row = idx >> 3, c16 = idx & 7;
    cp16(smem_u32(Asm_ + row * 144 + c16 * 16), Ag + (size_t)row * 128 + c16 * 16);
    cp16(smem_u32(Bsm_ + row * 144 + c16 * 16), Bg + (size_t)row * 128 + c16 * 16);
  }
  CP_COMMIT();
  CP_WAIT(0);
  __syncthreads();

  float acc[4][4][4];
#pragma unroll
  for (int i = 0; i < 4; i++)
#pragma unroll
    for (int j = 0; j < 4; j++)
#pragma unroll
      for (int v = 0; v < 4; v++) acc[i][j][v] = 0.f;

  const uint32_t* As = (const uint32_t*)Asm_;
  const uint32_t* Bs = (const uint32_t*)Bsm_;
#pragma unroll
  for (int kf = 0; kf < 4; kf++) {
    int fo = kf * 8;
    uint32_t a[4][4], b[4][2];
#pragma unroll
    for (int nf = 0; nf < 4; nf++) {
      int row = wk * 64 + nf * 16 + r;
      a[nf][0] = As[row * 36 + fo + tq];
      a[nf][1] = As[(row + 8) * 36 + fo + tq];
      a[nf][2] = As[row * 36 + fo + tq + 4];
      a[nf][3] = As[(row + 8) * 36 + fo + tq + 4];
    }
#pragma unroll
    for (int qf = 0; qf < 4; qf++) {
      int qr = wq * 32 + qf * 8 + r;
      b[qf][0] = Bs[qr * 36 + fo + tq];
      b[qf][1] = Bs[qr * 36 + fo + tq + 4];
    }
#pragma unroll
    for (int nf = 0; nf < 4; nf++)
#pragma unroll
      for (int qf = 0; qf < 4; qf++)
        mma16816(acc[nf][qf], a[nf][0], a[nf][1], a[nf][2], a[nf][3], b[qf][0], b[qf][1]);
  }

#pragma unroll
  for (int kf = 0; kf < 4; kf++)
#pragma unroll
    for (int qf = 0; qf < 4; qf++)
#pragma unroll
      for (int v = 0; v < 4; v++) acc[kf][qf][v] = __expf(acc[kf][qf][v]);

  float colp[4][2];
#pragma unroll
  for (int qf = 0; qf < 4; qf++) {
    colp[qf][0] = colp[qf][1] = 0.f;
#pragma unroll
    for (int kf = 0; kf < 4; kf++) {
      colp[qf][0] += acc[kf][qf][0] + acc[kf][qf][2];
      colp[qf][1] += acc[kf][qf][1] + acc[kf][qf][3];
    }
    colp[qf][0] += __shfl_xor_sync(0xffffffffu, colp[qf][0], 4);
    colp[qf][0] += __shfl_xor_sync(0xffffffffu, colp[qf][0], 8);
    colp[qf][0] += __shfl_xor_sync(0xffffffffu, colp[qf][0], 16);
    colp[qf][1] += __shfl_xor_sync(0xffffffffu, colp[qf][1], 4);
    colp[qf][1] += __shfl_xor_sync(0xffffffffu, colp[qf][1], 8);
    colp[qf][1] += __shfl_xor_sync(0xffffffffu, colp[qf][1], 16);
  }
  float* colsum = (float*)(SM + 36864);  // [2][128]
  if (lane < 4) {
#pragma unroll
    for (int qf = 0; qf < 4; qf++) {
      colsum[wk * 128 + wq * 32 + qf * 8 + 2 * tq + 0] = colp[qf][0];
      colsum[wk * 128 + wq * 32 + qf * 8 + 2 * tq + 1] = colp[qf][1];
    }
  }
  __syncthreads();
  if (t < 128) g_Prow[mat][kblk][q0 + t] = colsum[t] + colsum[128 + t];
}

// ---------------- K3: fused rowsum-reduce + V scale (bf16) ----------------
__global__ void __launch_bounds__(256) rsvscale_kernel() {
  __shared__ float rs_s[128];
  int mat = blockIdx.x >> 5, m0 = (blockIdx.x & 31) * 128;
  int t = threadIdx.x;
  if (t < 128) {
    float s = 0.f;
#pragma unroll
    for (int b = 0; b < 32; b++) s += g_Prow[mat][b][m0 + t];
    rs_s[t] = 1.0f / s;
  }
  __syncthreads();
  int c = t >> 2, g = t & 3;
  const float* Vp = &g_V[mat >> 1][c * N + m0 + g * 32];
  __nv_bfloat16* Op = &g_Vsb[mat][c * N + m0 + g * 32];
#pragma unroll
  for (int k = 0; k < 16; k++) {
    float v0 = Vp[2 * k] * rs_s[g * 32 + 2 * k];
    float v1 = Vp[2 * k + 1] * rs_s[g * 32 + 2 * k + 1];
    *(__nv_bfloat162*)&Op[2 * k] = __halves2bfloat162(__float2bfloat16(v0), __float2bfloat16(v1));
  }
}

// ---------------- K4 (pass 2): fused K=64 logits-recompute + exp + MP ----------------
__global__ void __launch_bounds__(256) fused_mp() {
  extern __shared__ __align__(16) char SM[];
  char* Kres = SM;                      // 128 x 144B = 18432
  char* Qb = SM + 18432;                // 3 x 18432 = 55296
  char* Vb = SM + 18432 + 55296;        // 3 x 17408 = 52224
  char* Stg = SM + 18432 + 55296 + 52224;  // 128 x 272B = 34816 (total 160768)
  int t = threadIdx.x, lane = t & 31, wid = t >> 5;
  int r = lane >> 2, tq = lane & 3;
  int wn = wid & 1, wm = wid >> 1;
  int wc2 = wid & 1, wn2 = wid >> 1;
  int nblk = blockIdx.x, mat = blockIdx.y;
  int n0 = nblk * 128;
  int qs = mat >> 1, ks = (mat == 1 || mat == 2) ? 1 : 0;
  const char* Kg = (const char*)&g_Kh2[ks][n0][0];
  const char* Qg = (const char*)&g_Qh2[qs][0][0];
  const char* Vg = (const char*)&g_Vsb[mat][0];

#pragma unroll
  for (int i = 0; i < 4; i++) {
    int idx = t + 256 * i, row = idx >> 3, c16 = idx & 7;
    cp16(smem_u32(Kres + row * 144 + c16 * 16), Kg + (size_t)row * 128 + c16 * 16);
  }
  CP_COMMIT();
#pragma unroll
  for (int p = 0; p < 2; p++) {
    char* q = Qb + p * 18432;
    char* v = Vb + p * 17408;
    int m0 = p * 128;
#pragma unroll
    for (int i = 0; i < 4; i++) {
      int idx = t + 256 * i, row = idx >> 3, c16 = idx & 7;
      cp16(smem_u32(q + row * 144 + c16 * 16), Qg + (size_t)(m0 + row) * 128 + c16 * 16);
    }
#pragma unroll
    for (int i = 0; i < 4; i++) {
      int idx = t + 256 * i, row = idx >> 4, c16 = idx & 15;
      cp16(smem_u32(v + row * 272 + c16 * 16), Vg + ((size_t)row * N + m0) * 2 + c16 * 16);
    }
    CP_COMMIT();
  }

  float accP[2][4][4];
#pragma unroll
  for (int i = 0; i < 2; i++)
#pragma unroll
    for (int j = 0; j < 4; j++)
#pragma unroll
      for (int v = 0; v < 4; v++) accP[i][j][v] = 0.f;

  for (int it = 0; it < 32; it++) {
    if (it == 31) { CP_WAIT(0); } else { CP_WAIT(1); }
    __syncthreads();

    const uint32_t* As = (const uint32_t*)Kres;
    const uint32_t* Bs = (const uint32_t*)(Qb + (it % 3) * 18432);
    float acc[4][4][4];
#pragma unroll
    for (int i = 0; i < 4; i++)
#pragma unroll
      for (int j = 0; j < 4; j++)
#pragma unroll
        for (int v = 0; v < 4; v++) acc[i][j][v] = 0.f;
#pragma unroll
    for (int kf = 0; kf < 4; kf++) {
      int fo = kf * 8;
      uint32_t a[4][4], b[4][2];
#pragma unroll
      for (int nf = 0; nf < 4; nf++) {
        int row = wn * 64 + nf * 16 + r;
        a[nf][0] = As[row * 36 + fo + tq];
        a[nf][1] = As[(row + 8) * 36 + fo + tq];
        a[nf][2] = As[row * 36 + fo + tq + 4];
        a[nf][3] = As[(row + 8) * 36 + fo + tq + 4];
      }
#pragma unroll
      for (int mf = 0; mf < 4; mf++) {
        int mr = wm * 32 + mf * 8 + r;
        b[mf][0] = Bs[mr * 36 + fo + tq];
        b[mf][1] = Bs[mr * 36 + fo + tq + 4];
      }
#pragma unroll
      for (int nf = 0; nf < 4; nf++)
#pragma unroll
        for (int mf = 0; mf < 4; mf++)
          mma16816(acc[nf][mf], a[nf][0], a[nf][1], a[nf][2], a[nf][3], b[mf][0], b[mf][1]);
    }
#pragma unroll
    for (int i = 0; i < 4; i++)
#pragma unroll
      for (int j = 0; j < 4; j++)
#pragma unroll
        for (int v = 0; v < 4; v++) acc[i][j][v] = __expf(acc[i][j][v]);

    {
      __nv_bfloat16* stg = (__nv_bfloat16*)Stg;
#pragma unroll
      for (int nf = 0; nf < 4; nf++)
#pragma unroll
        for (int mf = 0; mf < 4; mf++) {
          int n = wn * 64 + nf * 16 + r, m = wm * 32 + mf * 8 + 2 * tq;
          *(uint32_t*)&stg[n * 136 + m] = packbf(acc[nf][mf][0], acc[nf][mf][1]);
          *(uint32_t*)&stg[(n + 8) * 136 + m] = packbf(acc[nf][mf][2], acc[nf][mf][3]);
        }
    }
    __syncthreads();

    {
      const uint32_t* As2 = (const uint32_t*)(Vb + (it % 3) * 17408);
      const uint32_t* Bs2 = (const uint32_t*)Stg;
#pragma unroll
      for (int f2i = 0; f2i < 8; f2i++) {
        int fo = f2i * 8;
        uint32_t a2[2][4], b2[4][2];
#pragma unroll
        for (int cf = 0; cf < 2; cf++) {
          int row = wc2 * 32 + cf * 16 + r;
          a2[cf][0] = As2[row * 68 + fo + tq];
          a2[cf][1] = As2[(row + 8) * 68 + fo + tq];
          a2[cf][2] = As2[row * 68 + fo + tq + 4];
          a2[cf][3] = As2[(row + 8) * 68 + fo + tq + 4];
        }
#pragma unroll
        for (int nf2 = 0; nf2 < 4; nf2++) {
          int nr = wn2 * 32 + nf2 * 8 + r;
          b2[nf2][0] = Bs2[nr * 68 + fo + tq];
          b2[nf2][1] = Bs2[nr * 68 + fo + tq + 4];
        }
#pragma unroll
        for (int cf = 0; cf < 2; cf++)
#pragma unroll
          for (int nf2 = 0; nf2 < 4; nf2++)
            mma16816(accP[cf][nf2], a2[cf][0], a2[cf][1], a2[cf][2], a2[cf][3],
                     b2[nf2][0], b2[nf2][1]);
      }
    }
    if (it + 2 < 32) {
      char* q = Qb + ((it + 2) % 3) * 18432;
      char* v = Vb + ((it + 2) % 3) * 17408;
      int m0 = (it + 2) * 128;
#pragma unroll
      for (int i = 0; i < 4; i++) {
        int idx = t + 256 * i, row = idx >> 3, c16 = idx & 7;
        cp16(smem_u32(q + row * 144 + c16 * 16), Qg + (size_t)(m0 + row) * 128 + c16 * 16);
      }
#pragma unroll
      for (int i = 0; i < 4; i++) {
        int idx = t + 256 * i, row = idx >> 4, c16 = idx & 15;
        cp16(smem_u32(v + row * 272 + c16 * 16), Vg + ((size_t)row * N + m0) * 2 + c16 * 16);
      }
      CP_COMMIT();
    }
  }

#pragma unroll
  for (int cf = 0; cf < 2; cf++)
#pragma unroll
    for (int nf2 = 0; nf2 < 4; nf2++) {
      int ch = wc2 * 32 + cf * 16 + r, n = wn2 * 32 + nf2 * 8 + 2 * tq;
      *(float2*)&g_P[mat][ch * N + n0 + n] = make_float2(accP[cf][nf2][0], accP[cf][nf2][1]);
      *(float2*)&g_P[mat][(ch + 8) * N + n0 + n] = make_float2(accP[cf][nf2][2], accP[cf][nf2][3]);
    }
}

// ---------------- K5: Y = Wp * (P0 + P1 + X) ----------------
__global__ void __launch_bounds__(256) ygemm_kernel(
    const float* __restrict__ Xi, const float* __restrict__ Xj,
    const float* __restrict__ Wpi, const float* __restrict__ Wpj) {
  __shared__ float Ts[C][128];
  __shared__ float Wsm[C][C];
  int pair = blockIdx.y;
  const float* X = pair ? Xj : Xi;
  const float* Wp = pair ? Wpj : Wpi;
  int n0 = blockIdx.x * 128, t = threadIdx.x;
  for (int i = t; i < C * C / 4; i += 256)
    *(float4*)&Wsm[0][i * 4] = *(const float4*)&Wp[i * 4];
  for (int i = t; i < C * 32; i += 256) {
    int c = i >> 5, q = i & 31;
    float4 v = *(const float4*)&X[c * N + n0 + q * 4];
    float4 p0 = *(const float4*)&g_P[2 * pair][c * N + n0 + q * 4];
    float4 p1 = *(const float4*)&g_P[2 * pair + 1][c * N + n0 + q * 4];
    v.x += p0.x + p1.x; v.y += p0.y + p1.y; v.z += p0.z + p1.z; v.w += p0.w + p1.w;
    *(float4*)&Ts[c][q * 4] = v;
  }
  __syncthreads();
  int n = t & 127, h = t >> 7;
  float acc[32];
#pragma unroll
  for (int oo = 0; oo < 32; oo++) acc[oo] = 0.f;
  for (int c = 0; c < C; c++) {
    float x = Ts[c][n];
#pragma unroll
    for (int oo = 0; oo < 32; oo++) acc[oo] = fmaf(Wsm[h * 32 + oo][c], x, acc[oo]);
  }
#pragma unroll
  for (int oo = 0; oo < 32; oo++) g_Y[pair][(h * 32 + oo) * N + n0 + n] = acc[oo];
}

// ---------------- K6: BN stats ----------------
__global__ void bnstats_kernel() {
  int pair = blockIdx.x >> 6, c = blockIdx.x & 63;
  const float* y = &g_Y[pair][c * N];
  float s = 0.f, sq = 0.f;
  for (int n = threadIdx.x; n < N; n += 128) {
    float v = y[n];
    s += v; sq += v * v;
  }
  __shared__ float rs_[128], rq_[128];
  rs_[threadIdx.x] = s; rq_[threadIdx.x] = sq;
  __syncthreads();
  for (int off = 64; off > 0; off >>= 1) {
    if (threadIdx.x < off) {
      rs_[threadIdx.x] += rs_[threadIdx.x + off];
      rq_[threadIdx.x] += rq_[threadIdx.x + off];
    }
    __syncthreads();
  }
  if (threadIdx.x == 0) {
    float mean = rs_[0] * (1.0f / N);
    float var = rq_[0] * (1.0f / N) - mean * mean;
    g_bn[pair][0][c] = mean;
    g_bn[pair][1][c] = rsqrtf(var + 1e-5f);
  }
}

// ---------------- K7: BN + LeakyReLU + sum ----------------
__global__ void epilogue_kernel(const float* __restrict__ gi, const float* __restrict__ bi,
                                const float* __restrict__ gj, const float* __restrict__ bj,
                                float* __restrict__ out) {
  int id = blockIdx.x * 256 + threadIdx.x;
  int c = id >> 12;
  float yi = g_Y[0][id], yj = g_Y[1][id];
  float vi = (yi - g_bn[0][0][c]) * g_bn[0][1][c] * gi[c] + bi[c];
  float vj = (yj - g_bn[1][0][c]) * g_bn[1][1][c] * gj[c] + bj[c];
  vi = (vi >= 0.f) ? vi : 0.01f * vi;
  vj = (vj >= 0.f) ? vj : 0.01f * vj;
  out[id] = vi + vj;
}

// ---------------- launch ----------------
extern "C" void kernel_launch(void* const* d_in, const int* in_sizes, int n_in,
                              void* d_out, int out_size) {
  const float* Xi = (const float*)d_in[0];
  const float* Xj = (const float*)d_in[1];
  const float* Wq = (const float*)d_in[2];
  const float* Wk = (const float*)d_in[3];
  const float* Wv = (const float*)d_in[4];
  const float* Wpi = (const float*)d_in[5];
  const float* Wpj = (const float*)d_in[6];
  const float* gi = (const float*)d_in[7];
  const float* bi = (const float*)d_in[8];
  const float* gj = (const float*)d_in[9];
  const float* bj = (const float*)d_in[10];
  float* out = (float*)d_out;

  cudaFuncSetAttribute(fused_mp, cudaFuncAttributeMaxDynamicSharedMemorySize, 160768);

  qkv_kernel<<<dim3(32, 2), 256>>>(Xi, Xj, Wq, Wk, Wv);
  pass1_logits<<<dim3(32, 32, 4), 256>>>();
  rsvscale_kernel<<<128, 256>>>();
  fused_mp<<<dim3(32, 4), 256, 160768>>>();
  ygemm_kernel<<<dim3(32, 2), 256>>>(Xi, Xj, Wpi, Wpj);
  bnstats_kernel<<<128, 128>>>();
  epilogue_kernel<<<1024, 256>>>(gi, bi, gj, bj, out);
}